// round 1
// baseline (speedup 1.0000x reference)
#include <cuda_runtime.h>
#include <math.h>

// Problem constants: B=64, T=128, N=128, U=128
#define ROWS 8192   // B*T
#define NF   128    // feature dim (softmax axis)
#define Z_N  512    // 4*U
#define Q_N  256    // 2*U (query = [h, c])

// Scratch (device globals -- no allocations allowed)
__device__ float g_z[ROWS * Z_N];      // 16 MB
__device__ float g_query[ROWS * Q_N];  //  8 MB
__device__ float g_s2[ROWS * NF];      //  4 MB

__device__ __forceinline__ float tanh_fast(float x) {
    float y;
    asm("tanh.approx.f32 %0, %1;" : "=f"(y) : "f"(x));
    return y;
}

// ---------------------------------------------------------------------------
// Generic fp32 SIMT GEMM: C[M,N] = A[M,K] @ B[K,N] + bias[N]
// A, B, C row-major. BM,BN,BK tile; TM,TN per-thread micro-tile.
// ---------------------------------------------------------------------------
template<int BM, int BN, int BK, int TM, int TN>
__global__ void __launch_bounds__((BM/TM)*(BN/TN))
gemm_bias(const float* __restrict__ A, const float* __restrict__ B,
          const float* __restrict__ bias, float* __restrict__ C,
          int M, int N, int K)
{
    constexpr int THREADS = (BM/TM)*(BN/TN);
    __shared__ float As[BK][BM + 4];   // +4 pad: conflict-free transpose stores
    __shared__ float Bs[BK][BN];

    const int tid  = threadIdx.x;
    const int tx   = tid % (BN/TN);
    const int ty   = tid / (BN/TN);
    const int row0 = blockIdx.y * BM;
    const int col0 = blockIdx.x * BN;

    float acc[TM][TN];
    #pragma unroll
    for (int i = 0; i < TM; i++)
        #pragma unroll
        for (int j = 0; j < TN; j++) acc[i][j] = 0.f;

    for (int k0 = 0; k0 < K; k0 += BK) {
        // Load A tile (BM x BK) transposed into As[k][m]
        #pragma unroll
        for (int i = tid; i < BM*BK/4; i += THREADS) {
            int m  = i / (BK/4);
            int kq = i % (BK/4);
            float4 v = *reinterpret_cast<const float4*>(
                A + (size_t)(row0 + m) * K + k0 + kq * 4);
            As[kq*4+0][m] = v.x; As[kq*4+1][m] = v.y;
            As[kq*4+2][m] = v.z; As[kq*4+3][m] = v.w;
        }
        // Load B tile (BK x BN)
        #pragma unroll
        for (int i = tid; i < BK*BN/4; i += THREADS) {
            int k  = i / (BN/4);
            int nq = i % (BN/4);
            *reinterpret_cast<float4*>(&Bs[k][nq*4]) =
                *reinterpret_cast<const float4*>(
                    B + (size_t)(k0 + k) * N + col0 + nq * 4);
        }
        __syncthreads();

        #pragma unroll
        for (int k = 0; k < BK; k++) {
            float a[TM], b[TN];
            #pragma unroll
            for (int i = 0; i < TM; i += 4) {
                float4 v = *reinterpret_cast<const float4*>(&As[k][ty*TM + i]);
                a[i] = v.x; a[i+1] = v.y; a[i+2] = v.z; a[i+3] = v.w;
            }
            #pragma unroll
            for (int j = 0; j < TN; j += 4) {
                float4 v = *reinterpret_cast<const float4*>(&Bs[k][tx*TN + j]);
                b[j] = v.x; b[j+1] = v.y; b[j+2] = v.z; b[j+3] = v.w;
            }
            #pragma unroll
            for (int i = 0; i < TM; i++)
                #pragma unroll
                for (int j = 0; j < TN; j++)
                    acc[i][j] = fmaf(a[i], b[j], acc[i][j]);
        }
        __syncthreads();
    }

    #pragma unroll
    for (int i = 0; i < TM; i++) {
        #pragma unroll
        for (int j = 0; j < TN; j += 4) {
            float4 o;
            int c = col0 + tx*TN + j;
            o.x = acc[i][j+0] + bias[c+0];
            o.y = acc[i][j+1] + bias[c+1];
            o.z = acc[i][j+2] + bias[c+2];
            o.w = acc[i][j+3] + bias[c+3];
            *reinterpret_cast<float4*>(
                C + (size_t)(row0 + ty*TM + i) * N + c) = o;
        }
    }
}

// ---------------------------------------------------------------------------
// Gates: z[row, 0:128]=i, [256:384]=g, [384:512]=o (f drops: c_prev = 0).
// c = sigmoid(i)*tanh(g); h = sigmoid(o)*tanh(c); query = [h, c]
// ---------------------------------------------------------------------------
__global__ void gates_kernel(const float* __restrict__ z, float* __restrict__ q)
{
    int idx = blockIdx.x * blockDim.x + threadIdx.x;   // < ROWS*128
    int row = idx >> 7;
    int u   = idx & 127;
    const float* zr = z + (size_t)row * Z_N;
    float iv = zr[u];
    float gv = zr[256 + u];
    float ov = zr[384 + u];
    float si = 1.f / (1.f + __expf(-iv));
    float c  = si * tanhf(gv);
    float so = 1.f / (1.f + __expf(-ov));
    float h  = so * tanhf(c);
    q[(size_t)row * Q_N + u]       = h;
    q[(size_t)row * Q_N + 128 + u] = c;
}

// ---------------------------------------------------------------------------
// Attention: one block per row. e_n = sum_k tanh(x_n*w1[k] + (w1b[k]+s2[k]))*v[k]
// then softmax over n, out = x * alpha. (v_bias is softmax-invariant.)
// ---------------------------------------------------------------------------
__global__ void __launch_bounds__(128)
attn_kernel(const float* __restrict__ x, const float* __restrict__ s2,
            const float* __restrict__ w1, const float* __restrict__ w1b,
            const float* __restrict__ v, float* __restrict__ out)
{
    __shared__ float4 pk[128];
    __shared__ float redm[4], reds[4];

    const int row = blockIdx.x;
    const int n   = threadIdx.x;

    float xv = x[(size_t)row * NF + n];
    pk[n] = make_float4(w1[n], w1b[n] + s2[(size_t)row * NF + n], v[n], 0.f);
    __syncthreads();

    float a0 = 0.f, a1 = 0.f, a2 = 0.f, a3 = 0.f;
    #pragma unroll 4
    for (int k = 0; k < 128; k += 4) {
        float4 p0 = pk[k+0];
        float4 p1 = pk[k+1];
        float4 p2 = pk[k+2];
        float4 p3 = pk[k+3];
        a0 = fmaf(tanh_fast(fmaf(xv, p0.x, p0.y)), p0.z, a0);
        a1 = fmaf(tanh_fast(fmaf(xv, p1.x, p1.y)), p1.z, a1);
        a2 = fmaf(tanh_fast(fmaf(xv, p2.x, p2.y)), p2.z, a2);
        a3 = fmaf(tanh_fast(fmaf(xv, p3.x, p3.y)), p3.z, a3);
    }
    float e = (a0 + a1) + (a2 + a3);

    // softmax over the 128 threads
    int lane = n & 31, wid = n >> 5;
    float m = e;
    #pragma unroll
    for (int o = 16; o > 0; o >>= 1)
        m = fmaxf(m, __shfl_xor_sync(0xffffffffu, m, o));
    if (lane == 0) redm[wid] = m;
    __syncthreads();
    m = fmaxf(fmaxf(redm[0], redm[1]), fmaxf(redm[2], redm[3]));

    float p = __expf(e - m);
    float s = p;
    #pragma unroll
    for (int o = 16; o > 0; o >>= 1)
        s += __shfl_xor_sync(0xffffffffu, s, o);
    if (lane == 0) reds[wid] = s;
    __syncthreads();
    s = (reds[0] + reds[1]) + (reds[2] + reds[3]);

    out[(size_t)row * NF + n] = xv * (p / s);
}

// ---------------------------------------------------------------------------
extern "C" void kernel_launch(void* const* d_in, const int* in_sizes, int n_in,
                              void* d_out, int out_size)
{
    const float* x   = (const float*)d_in[0];
    // d_in[1]=hidden_state, d_in[2]=cell_state: unused (LSTM resets each step)
    const float* Wl  = (const float*)d_in[3];   // (128, 512)
    const float* bl  = (const float*)d_in[4];   // (512)
    const float* w1  = (const float*)d_in[5];   // (128)
    const float* w1b = (const float*)d_in[6];   // (128)
    const float* W2  = (const float*)d_in[7];   // (256, 128)
    const float* b2  = (const float*)d_in[8];   // (128)
    const float* v   = (const float*)d_in[9];   // (128)
    // d_in[10]=v_bias (softmax-invariant), d_in[11]=n (constant 128)
    float* out = (float*)d_out;

    float *z_ptr, *q_ptr, *s2_ptr;
    cudaGetSymbolAddress((void**)&z_ptr,  g_z);
    cudaGetSymbolAddress((void**)&q_ptr,  g_query);
    cudaGetSymbolAddress((void**)&s2_ptr, g_s2);

    // K1: z = x @ lstm_kernel + lstm_bias   (8192 x 512 x 128)
    gemm_bias<128,128,32,8,8><<<dim3(Z_N/128, ROWS/128), 256>>>(
        x, Wl, bl, z_ptr, ROWS, Z_N, NF);

    // K2: gates -> query = [h, c]
    gates_kernel<<<ROWS * 128 / 256, 256>>>(z_ptr, q_ptr);

    // K3: s2 = query @ w2_kernel + w2_bias  (8192 x 128 x 256)
    gemm_bias<64,128,32,4,8><<<dim3(NF/128, ROWS/64), 256>>>(
        q_ptr, W2, b2, s2_ptr, ROWS, NF, Q_N);

    // K4: fused attention score + softmax + scale
    attn_kernel<<<ROWS, 128>>>(x, s2_ptr, w1, w1b, v, out);
}

// round 3
// speedup vs baseline: 1.2725x; 1.2725x over previous
#include <cuda_runtime.h>
#include <cstdint>
#include <math.h>

// Problem constants: B=64, T=128, N=128, U=128
#define ROWS 8192   // B*T
#define NF   128

// Scratch (device globals -- no allocations allowed)
__device__ float  g_query[ROWS * 256];        // [h, c] per row
__device__ float  g_s2[ROWS * 128];
__device__ float2 g_Bf1[16 * 48 * 32];        // Wl prepacked frags (K=128, N=384)
__device__ float2 g_Bf2[32 * 16 * 32];        // W2 prepacked frags (K=256, N=128)

// ---------------------------------------------------------------------------
// helpers
// ---------------------------------------------------------------------------
__device__ __forceinline__ float tanh_fast(float x) {
    float y;
    asm("tanh.approx.f32 %0, %1;" : "=f"(y) : "f"(x));
    return y;
}
__device__ __forceinline__ uint32_t f2tf32(float f) {
    uint32_t u;
    asm("cvt.rna.tf32.f32 %0, %1;" : "=r"(u) : "f"(f));
    return u;
}
__device__ __forceinline__ void mma_tf32(float c[4], uint32_t a0, uint32_t a1,
                                         uint32_t a2, uint32_t a3,
                                         uint32_t b0, uint32_t b1) {
    asm volatile(
        "mma.sync.aligned.m16n8k8.row.col.f32.tf32.tf32.f32 "
        "{%0,%1,%2,%3}, {%4,%5,%6,%7}, {%8,%9}, {%0,%1,%2,%3};"
        : "+f"(c[0]), "+f"(c[1]), "+f"(c[2]), "+f"(c[3])
        : "r"(a0), "r"(a1), "r"(a2), "r"(a3), "r"(b0), "r"(b1));
}

// ---------------------------------------------------------------------------
// Prepack Wl (128x512) -> frag-ordered tf32 float2, skipping dead f-gate cols.
// packed col n (0..383): orig col = n + (n>=128 ? 128 : 0)  [i | g | o]
// tile (t=k0/8, j=n0/8), lane l: e0=W[t*8 + l%4][col], e1=W[t*8+4+l%4][col],
// col from n = j*8 + l/4. Stored at Bf[(t*48 + j)*32 + l].
// ---------------------------------------------------------------------------
__global__ void pack_wl(const float* __restrict__ W, float2* __restrict__ Bf)
{
    int idx = blockIdx.x * 256 + threadIdx.x;           // < 16*48*32
    int t = idx / (48 * 32);
    int rem = idx % (48 * 32);
    int j = rem >> 5, l = rem & 31;
    int n = j * 8 + (l >> 2);
    int col = n + ((n >= 128) ? 128 : 0);
    int k = t * 8 + (l & 3);
    float e0 = W[(size_t)k * 512 + col];
    float e1 = W[(size_t)(k + 4) * 512 + col];
    float2 o;
    o.x = __uint_as_float(f2tf32(e0));
    o.y = __uint_as_float(f2tf32(e1));
    Bf[idx] = o;
}

// Prepack W2 (256x128) -> frag-ordered tf32 float2 (direct col mapping).
__global__ void pack_w2(const float* __restrict__ W, float2* __restrict__ Bf)
{
    int idx = blockIdx.x * 256 + threadIdx.x;           // < 32*16*32
    int t = idx / (16 * 32);
    int rem = idx % (16 * 32);
    int j = rem >> 5, l = rem & 31;
    int n = j * 8 + (l >> 2);
    int k = t * 8 + (l & 3);
    float e0 = W[(size_t)k * 128 + n];
    float e1 = W[(size_t)(k + 4) * 128 + n];
    float2 o;
    o.x = __uint_as_float(f2tf32(e0));
    o.y = __uint_as_float(f2tf32(e1));
    Bf[idx] = o;
}

// ---------------------------------------------------------------------------
// K1: z = x @ Wl_packed (8192 x 384, K=128) via tf32 mma.sync,
// gates fused through an smem tile -> query = [h, c]. One CTA = 16 rows,
// 6 warps = 6 x 64-col groups. Bias added at gate stage.
// ---------------------------------------------------------------------------
#define ZS_STRIDE 388   // 384 + 4 pad (4-bank row shift kills STS conflicts)

__global__ void __launch_bounds__(192)
gemm_lstm(const float* __restrict__ A, const float2* __restrict__ Bf,
          const float* __restrict__ bl, float* __restrict__ query)
{
    __shared__ float zs[16 * ZS_STRIDE];

    const int lane = threadIdx.x & 31;
    const int w    = threadIdx.x >> 5;      // 0..5
    const int r0   = blockIdx.x * 16;
    const int n0   = w * 64;

    float c[8][4];
    #pragma unroll
    for (int j = 0; j < 8; ++j)
        #pragma unroll
        for (int e = 0; e < 4; ++e) c[j][e] = 0.f;

    const float* a_base = A + (size_t)(r0 + (lane >> 2)) * 128 + (lane & 3);

    #pragma unroll
    for (int t = 0; t < 16; ++t) {
        const float* ap = a_base + t * 8;
        uint32_t a0 = f2tf32(ap[0]);
        uint32_t a1 = f2tf32(ap[8 * 128]);
        uint32_t a2 = f2tf32(ap[4]);
        uint32_t a3 = f2tf32(ap[8 * 128 + 4]);
        const float2* bp = Bf + (size_t)(t * 48 + w * 8) * 32 + lane;
        #pragma unroll
        for (int j = 0; j < 8; ++j) {
            float2 b = bp[j * 32];
            mma_tf32(c[j], a0, a1, a2, a3,
                     __float_as_uint(b.x), __float_as_uint(b.y));
        }
    }

    // Stage z tile into smem
    const int crow = lane >> 2;
    const int ccol = n0 + 2 * (lane & 3);
    #pragma unroll
    for (int j = 0; j < 8; ++j) {
        int col = ccol + j * 8;
        *reinterpret_cast<float2*>(&zs[crow * ZS_STRIDE + col]) =
            make_float2(c[j][0], c[j][1]);
        *reinterpret_cast<float2*>(&zs[(crow + 8) * ZS_STRIDE + col]) =
            make_float2(c[j][2], c[j][3]);
    }
    __syncthreads();

    // Gates: i = z[:,u], g = z[:,128+u], o = z[:,256+u]
    for (int idx = threadIdx.x; idx < 16 * 128; idx += 192) {
        int row = idx >> 7, u = idx & 127;
        const float* zr = &zs[row * ZS_STRIDE];
        float iv = zr[u]       + bl[u];
        float gv = zr[128 + u] + bl[256 + u];
        float ov = zr[256 + u] + bl[384 + u];
        float si = 0.5f * tanh_fast(0.5f * iv) + 0.5f;
        float cc = si * tanh_fast(gv);
        float so = 0.5f * tanh_fast(0.5f * ov) + 0.5f;
        float h  = so * tanh_fast(cc);
        size_t qb = (size_t)(r0 + row) * 256 + u;
        query[qb]       = h;
        query[qb + 128] = cc;
    }
}

// ---------------------------------------------------------------------------
// K3: s2 = query (8192 x 256) @ W2 (256 x 128) + b2, tf32 mma.sync.
// 4 warps/CTA; warp = (strip, 64-col half).
// ---------------------------------------------------------------------------
__global__ void __launch_bounds__(128)
gemm_s2(const float* __restrict__ A, const float2* __restrict__ Bf,
        const float* __restrict__ b2, float* __restrict__ s2)
{
    const int lane = threadIdx.x & 31;
    const int w    = threadIdx.x >> 5;
    const int gw   = blockIdx.x * 4 + w;
    const int r0   = (gw >> 1) * 16;
    const int n0   = (gw & 1) * 64;

    float c[8][4];
    #pragma unroll
    for (int j = 0; j < 8; ++j)
        #pragma unroll
        for (int e = 0; e < 4; ++e) c[j][e] = 0.f;

    const float* a_base = A + (size_t)(r0 + (lane >> 2)) * 256 + (lane & 3);

    #pragma unroll 8
    for (int t = 0; t < 32; ++t) {
        const float* ap = a_base + t * 8;
        uint32_t a0 = f2tf32(ap[0]);
        uint32_t a1 = f2tf32(ap[8 * 256]);
        uint32_t a2 = f2tf32(ap[4]);
        uint32_t a3 = f2tf32(ap[8 * 256 + 4]);
        const float2* bp = Bf + (size_t)(t * 16 + (n0 >> 3)) * 32 + lane;
        #pragma unroll
        for (int j = 0; j < 8; ++j) {
            float2 b = bp[j * 32];
            mma_tf32(c[j], a0, a1, a2, a3,
                     __float_as_uint(b.x), __float_as_uint(b.y));
        }
    }

    const int crow = lane >> 2;
    const int ccol = n0 + 2 * (lane & 3);
    #pragma unroll
    for (int j = 0; j < 8; ++j) {
        int col = ccol + j * 8;
        float bx = b2[col], by = b2[col + 1];
        *reinterpret_cast<float2*>(&s2[(size_t)(r0 + crow) * 128 + col]) =
            make_float2(c[j][0] + bx, c[j][1] + by);
        *reinterpret_cast<float2*>(&s2[(size_t)(r0 + crow + 8) * 128 + col]) =
            make_float2(c[j][2] + bx, c[j][3] + by);
    }
}

// ---------------------------------------------------------------------------
// attn: e_n = sum_k tanh(x_n*w1[k] + (w1b[k]+s2[k]))*v[k]; softmax; out=x*alpha
// (MUFU-floor bound; unchanged from round 1)
// ---------------------------------------------------------------------------
__global__ void __launch_bounds__(128)
attn_kernel(const float* __restrict__ x, const float* __restrict__ s2,
            const float* __restrict__ w1, const float* __restrict__ w1b,
            const float* __restrict__ v, float* __restrict__ out)
{
    __shared__ float4 pk[128];
    __shared__ float redm[4], reds[4];

    const int row = blockIdx.x;
    const int n   = threadIdx.x;

    float xv = x[(size_t)row * NF + n];
    pk[n] = make_float4(w1[n], w1b[n] + s2[(size_t)row * NF + n], v[n], 0.f);
    __syncthreads();

    float a0 = 0.f, a1 = 0.f, a2 = 0.f, a3 = 0.f;
    #pragma unroll 4
    for (int k = 0; k < 128; k += 4) {
        float4 p0 = pk[k+0], p1 = pk[k+1], p2 = pk[k+2], p3 = pk[k+3];
        a0 = fmaf(tanh_fast(fmaf(xv, p0.x, p0.y)), p0.z, a0);
        a1 = fmaf(tanh_fast(fmaf(xv, p1.x, p1.y)), p1.z, a1);
        a2 = fmaf(tanh_fast(fmaf(xv, p2.x, p2.y)), p2.z, a2);
        a3 = fmaf(tanh_fast(fmaf(xv, p3.x, p3.y)), p3.z, a3);
    }
    float e = (a0 + a1) + (a2 + a3);

    int lane = n & 31, wd = n >> 5;
    float m = e;
    #pragma unroll
    for (int o = 16; o > 0; o >>= 1)
        m = fmaxf(m, __shfl_xor_sync(0xffffffffu, m, o));
    if (lane == 0) redm[wd] = m;
    __syncthreads();
    m = fmaxf(fmaxf(redm[0], redm[1]), fmaxf(redm[2], redm[3]));

    float pr = __expf(e - m);
    float s = pr;
    #pragma unroll
    for (int o = 16; o > 0; o >>= 1)
        s += __shfl_xor_sync(0xffffffffu, s, o);
    if (lane == 0) reds[wd] = s;
    __syncthreads();
    s = (reds[0] + reds[1]) + (reds[2] + reds[3]);

    out[(size_t)row * NF + n] = xv * (pr / s);
}

// ---------------------------------------------------------------------------
extern "C" void kernel_launch(void* const* d_in, const int* in_sizes, int n_in,
                              void* d_out, int out_size)
{
    const float* x   = (const float*)d_in[0];
    const float* Wl  = (const float*)d_in[3];   // (128, 512)
    const float* bl  = (const float*)d_in[4];   // (512)
    const float* w1  = (const float*)d_in[5];   // (128)
    const float* w1b = (const float*)d_in[6];   // (128)
    const float* W2  = (const float*)d_in[7];   // (256, 128)
    const float* b2  = (const float*)d_in[8];   // (128)
    const float* v   = (const float*)d_in[9];   // (128)
    float* out = (float*)d_out;

    float *q_ptr, *s2_ptr;
    float2 *bf1, *bf2;
    cudaGetSymbolAddress((void**)&q_ptr,  g_query);
    cudaGetSymbolAddress((void**)&s2_ptr, g_s2);
    cudaGetSymbolAddress((void**)&bf1,    g_Bf1);
    cudaGetSymbolAddress((void**)&bf2,    g_Bf2);

    pack_wl<<<96, 256>>>(Wl, bf1);      // 16*48*32 / 256
    pack_w2<<<64, 256>>>(W2, bf2);      // 32*16*32 / 256

    gemm_lstm<<<ROWS / 16, 192>>>(x, bf1, bl, q_ptr);
    gemm_s2<<<ROWS / 16 / 2, 128>>>(q_ptr, bf2, b2, s2_ptr);
    attn_kernel<<<ROWS, 128>>>(x, s2_ptr, w1, w1b, v, out);
}

// round 4
// speedup vs baseline: 1.8112x; 1.4233x over previous
#include <cuda_runtime.h>
#include <cstdint>
#include <math.h>

// Problem constants: B=64, T=128, N=128, U=128
#define ROWS 8192   // B*T

// Prepacked weight fragments (device globals -- no allocations allowed)
__device__ float2 g_Bf1[16 * 48 * 32];   // Wl packed (K=128, N=384, f-gate dropped)
__device__ float2 g_Bf2[32 * 16 * 32];   // W2 packed (K=256, N=128)

// ---------------------------------------------------------------------------
// helpers
// ---------------------------------------------------------------------------
__device__ __forceinline__ float tanh_fast(float x) {
    float y;
    asm("tanh.approx.f32 %0, %1;" : "=f"(y) : "f"(x));
    return y;
}
__device__ __forceinline__ uint32_t f2tf32(float f) {
    uint32_t u;
    asm("cvt.rna.tf32.f32 %0, %1;" : "=r"(u) : "f"(f));
    return u;
}
__device__ __forceinline__ void mma_tf32(float c[4], uint32_t a0, uint32_t a1,
                                         uint32_t a2, uint32_t a3,
                                         uint32_t b0, uint32_t b1) {
    asm volatile(
        "mma.sync.aligned.m16n8k8.row.col.f32.tf32.tf32.f32 "
        "{%0,%1,%2,%3}, {%4,%5,%6,%7}, {%8,%9}, {%0,%1,%2,%3};"
        : "+f"(c[0]), "+f"(c[1]), "+f"(c[2]), "+f"(c[3])
        : "r"(a0), "r"(a1), "r"(a2), "r"(a3), "r"(b0), "r"(b1));
}

// ---------------------------------------------------------------------------
// Prepack Wl (128x512) -> frag-ordered tf32 float2, skipping dead f-gate cols.
// packed col n (0..383): orig col = n + (n>=128 ? 128 : 0)   [i | g | o]
// ---------------------------------------------------------------------------
__global__ void pack_wl(const float* __restrict__ W, float2* __restrict__ Bf)
{
    int idx = blockIdx.x * 256 + threadIdx.x;           // < 16*48*32
    int t = idx / (48 * 32);
    int rem = idx % (48 * 32);
    int j = rem >> 5, l = rem & 31;
    int n = j * 8 + (l >> 2);
    int col = n + ((n >= 128) ? 128 : 0);
    int k = t * 8 + (l & 3);
    float2 o;
    o.x = __uint_as_float(f2tf32(W[(size_t)k * 512 + col]));
    o.y = __uint_as_float(f2tf32(W[(size_t)(k + 4) * 512 + col]));
    Bf[idx] = o;
}

__global__ void pack_w2(const float* __restrict__ W, float2* __restrict__ Bf)
{
    int idx = blockIdx.x * 256 + threadIdx.x;           // < 32*16*32
    int t = idx / (16 * 32);
    int rem = idx % (16 * 32);
    int j = rem >> 5, l = rem & 31;
    int n = j * 8 + (l >> 2);
    int k = t * 8 + (l & 3);
    float2 o;
    o.x = __uint_as_float(f2tf32(W[(size_t)k * 128 + n]));
    o.y = __uint_as_float(f2tf32(W[(size_t)(k + 4) * 128 + n]));
    Bf[idx] = o;
}

// ---------------------------------------------------------------------------
// Fused encoder: per CTA = 16 rows, 256 threads (8 warps).
//   Phase B: z = x @ Wl (tf32 mma, N=384) -> smem
//   gates   : query = [h, c] -> smem (never hits DRAM)
//   Phase C: s2 = query @ W2 (+b2 +w1b) -> smem
//   Phase D: e_n = sum_k tanh(x_n*w1_k + base_k) * v_k; softmax; out = x*alpha
// ---------------------------------------------------------------------------
#define XS  132   // x strip stride (floats)
#define ZSs 388   // z tile stride
#define QS  260   // query stride
#define SS  132   // s2/base stride

#define OFF_X   0
#define OFF_ZS  (16 * XS)             // 2112
#define OFF_Q   (OFF_ZS + 16 * ZSs)   // 8320
#define OFF_S2  (OFF_Q + 16 * QS)     // 12480
#define OFF_WV  (OFF_S2 + 16 * SS)    // 14592
#define SMEM_FLOATS (OFF_WV + 256)    // 14848 -> 59392 bytes

__global__ void __launch_bounds__(256)
fused_enc(const float* __restrict__ x,
          const float2* __restrict__ Bf1, const float2* __restrict__ Bf2,
          const float* __restrict__ bl,  const float* __restrict__ b2,
          const float* __restrict__ w1,  const float* __restrict__ w1b,
          const float* __restrict__ v,   float* __restrict__ out)
{
    extern __shared__ float sm[];
    float*  X  = sm + OFF_X;
    float*  ZS = sm + OFF_ZS;
    float*  Q  = sm + OFF_Q;
    float*  S2 = sm + OFF_S2;
    float2* WV = reinterpret_cast<float2*>(sm + OFF_WV);

    const int tid  = threadIdx.x;
    const int lane = tid & 31;
    const int w    = tid >> 5;          // 0..7
    const int r0   = blockIdx.x * 16;

    // ---- load x strip (16 x 128) and (w1, v) pairs ----
    #pragma unroll
    for (int it = 0; it < 2; ++it) {
        int i = it * 256 + tid;          // < 512
        int row = i >> 5, q4 = i & 31;
        float4 vv = *reinterpret_cast<const float4*>(
            x + (size_t)(r0 + row) * 128 + q4 * 4);
        *reinterpret_cast<float4*>(&X[row * XS + q4 * 4]) = vv;
    }
    if (tid < 128) WV[tid] = make_float2(w1[tid], v[tid]);
    __syncthreads();

    // ---- Phase B: z GEMM (16 x 384, K=128). warp w -> cols [w*48, w*48+48) ----
    {
        float acc[6][4];
        #pragma unroll
        for (int j = 0; j < 6; ++j)
            #pragma unroll
            for (int e = 0; e < 4; ++e) acc[j][e] = 0.f;

        const int arow = lane >> 2, acol0 = lane & 3;
        #pragma unroll
        for (int t = 0; t < 16; ++t) {
            int ac = acol0 + t * 8;
            uint32_t a0 = f2tf32(X[arow * XS + ac]);
            uint32_t a1 = f2tf32(X[(arow + 8) * XS + ac]);
            uint32_t a2 = f2tf32(X[arow * XS + ac + 4]);
            uint32_t a3 = f2tf32(X[(arow + 8) * XS + ac + 4]);
            const float2* bp = Bf1 + (size_t)(t * 48 + w * 6) * 32 + lane;
            #pragma unroll
            for (int j = 0; j < 6; ++j) {
                float2 b = bp[j * 32];
                mma_tf32(acc[j], a0, a1, a2, a3,
                         __float_as_uint(b.x), __float_as_uint(b.y));
            }
        }
        const int crow = lane >> 2, cc = 2 * (lane & 3);
        #pragma unroll
        for (int j = 0; j < 6; ++j) {
            int col = w * 48 + j * 8 + cc;
            *reinterpret_cast<float2*>(&ZS[crow * ZSs + col]) =
                make_float2(acc[j][0], acc[j][1]);
            *reinterpret_cast<float2*>(&ZS[(crow + 8) * ZSs + col]) =
                make_float2(acc[j][2], acc[j][3]);
        }
    }
    __syncthreads();

    // ---- gates: query = [h, c] ----
    #pragma unroll
    for (int it = 0; it < 8; ++it) {
        int i = it * 256 + tid;          // < 2048
        int row = i >> 7, u = i & 127;
        const float* zr = &ZS[row * ZSs];
        float iv = zr[u]       + bl[u];
        float gv = zr[128 + u] + bl[256 + u];
        float ov = zr[256 + u] + bl[384 + u];
        float si = 0.5f * tanh_fast(0.5f * iv) + 0.5f;
        float cc = si * tanh_fast(gv);
        float so = 0.5f * tanh_fast(0.5f * ov) + 0.5f;
        Q[row * QS + u]       = so * tanh_fast(cc);
        Q[row * QS + 128 + u] = cc;
    }
    __syncthreads();

    // ---- Phase C: s2 GEMM (16 x 128, K=256). warp w -> cols [w*16, w*16+16) ----
    {
        float acc[2][4];
        #pragma unroll
        for (int j = 0; j < 2; ++j)
            #pragma unroll
            for (int e = 0; e < 4; ++e) acc[j][e] = 0.f;

        const int arow = lane >> 2, acol0 = lane & 3;
        #pragma unroll
        for (int t = 0; t < 32; ++t) {
            int ac = acol0 + t * 8;
            uint32_t a0 = f2tf32(Q[arow * QS + ac]);
            uint32_t a1 = f2tf32(Q[(arow + 8) * QS + ac]);
            uint32_t a2 = f2tf32(Q[arow * QS + ac + 4]);
            uint32_t a3 = f2tf32(Q[(arow + 8) * QS + ac + 4]);
            const float2* bp = Bf2 + (size_t)(t * 16 + w * 2) * 32 + lane;
            #pragma unroll
            for (int j = 0; j < 2; ++j) {
                float2 b = bp[j * 32];
                mma_tf32(acc[j], a0, a1, a2, a3,
                         __float_as_uint(b.x), __float_as_uint(b.y));
            }
        }
        // store base = s2 + b2 + w1b
        const int crow = lane >> 2, cc = 2 * (lane & 3);
        #pragma unroll
        for (int j = 0; j < 2; ++j) {
            int col = w * 16 + j * 8 + cc;
            float bb0 = b2[col]     + w1b[col];
            float bb1 = b2[col + 1] + w1b[col + 1];
            *reinterpret_cast<float2*>(&S2[crow * SS + col]) =
                make_float2(acc[j][0] + bb0, acc[j][1] + bb1);
            *reinterpret_cast<float2*>(&S2[(crow + 8) * SS + col]) =
                make_float2(acc[j][2] + bb0, acc[j][3] + bb1);
        }
    }
    __syncthreads();

    // ---- Phase D: attention. thread -> (row = tid/16, 8 n's strided by 16) ----
    {
        const int row = tid >> 4;
        const int nb  = tid & 15;
        const float* xr = &X[row * XS + nb];
        const float* br = &S2[row * SS];

        float xv[8], ea[8];
        #pragma unroll
        for (int j = 0; j < 8; ++j) { xv[j] = xr[16 * j]; ea[j] = 0.f; }

        #pragma unroll 4
        for (int k = 0; k < 128; ++k) {
            float2 wv = WV[k];
            float  bb = br[k];
            #pragma unroll
            for (int j = 0; j < 8; ++j)
                ea[j] = fmaf(tanh_fast(fmaf(xv[j], wv.x, bb)), wv.y, ea[j]);
        }

        // softmax over the row's 128 n's (16 lanes x 8 regs)
        float m = ea[0];
        #pragma unroll
        for (int j = 1; j < 8; ++j) m = fmaxf(m, ea[j]);
        #pragma unroll
        for (int o = 8; o > 0; o >>= 1)
            m = fmaxf(m, __shfl_xor_sync(0xffffffffu, m, o));

        float p[8], s = 0.f;
        #pragma unroll
        for (int j = 0; j < 8; ++j) { p[j] = __expf(ea[j] - m); s += p[j]; }
        #pragma unroll
        for (int o = 8; o > 0; o >>= 1)
            s += __shfl_xor_sync(0xffffffffu, s, o);
        float inv = 1.f / s;

        float* orow = out + (size_t)(r0 + row) * 128 + nb;
        #pragma unroll
        for (int j = 0; j < 8; ++j)
            orow[16 * j] = xv[j] * p[j] * inv;
    }
}

// ---------------------------------------------------------------------------
extern "C" void kernel_launch(void* const* d_in, const int* in_sizes, int n_in,
                              void* d_out, int out_size)
{
    const float* x   = (const float*)d_in[0];
    const float* Wl  = (const float*)d_in[3];   // (128, 512)
    const float* bl  = (const float*)d_in[4];   // (512)
    const float* w1  = (const float*)d_in[5];   // (128)
    const float* w1b = (const float*)d_in[6];   // (128)
    const float* W2  = (const float*)d_in[7];   // (256, 128)
    const float* b2  = (const float*)d_in[8];   // (128)
    const float* v   = (const float*)d_in[9];   // (128)
    float* out = (float*)d_out;

    float2 *bf1, *bf2;
    cudaGetSymbolAddress((void**)&bf1, g_Bf1);
    cudaGetSymbolAddress((void**)&bf2, g_Bf2);

    static int smem_set = 0;
    if (!smem_set) {
        cudaFuncSetAttribute(fused_enc,
            cudaFuncAttributeMaxDynamicSharedMemorySize, SMEM_FLOATS * 4);
        smem_set = 1;
    }

    pack_wl<<<96, 256>>>(Wl, bf1);
    pack_w2<<<64, 256>>>(W2, bf2);
    fused_enc<<<ROWS / 16, 256, SMEM_FLOATS * 4>>>(
        x, bf1, bf2, bl, b2, w1, w1b, v, out);
}

// round 5
// speedup vs baseline: 1.9478x; 1.0754x over previous
#include <cuda_runtime.h>
#include <cstdint>
#include <math.h>

// Problem constants: B=64, T=128, N=128, U=128
#define ROWS 8192   // B*T

// Prepacked weight fragments (device globals -- no allocations allowed)
__device__ float2 g_Bf1[16 * 48 * 32];   // Wl packed (K=128, N=384, gate-interleaved)
__device__ float2 g_Bf2[32 * 16 * 32];   // W2 packed (K=256, N=128)

// ---------------------------------------------------------------------------
// helpers
// ---------------------------------------------------------------------------
__device__ __forceinline__ float tanh_fast(float x) {
    float y;
    asm("tanh.approx.f32 %0, %1;" : "=f"(y) : "f"(x));
    return y;
}
__device__ __forceinline__ uint32_t f2tf32(float f) {
    uint32_t u;
    asm("cvt.rna.tf32.f32 %0, %1;" : "=r"(u) : "f"(f));
    return u;
}
__device__ __forceinline__ void mma_tf32(float c[4], uint32_t a0, uint32_t a1,
                                         uint32_t a2, uint32_t a3,
                                         uint32_t b0, uint32_t b1) {
    asm volatile(
        "mma.sync.aligned.m16n8k8.row.col.f32.tf32.tf32.f32 "
        "{%0,%1,%2,%3}, {%4,%5,%6,%7}, {%8,%9}, {%0,%1,%2,%3};"
        : "+f"(c[0]), "+f"(c[1]), "+f"(c[2]), "+f"(c[3])
        : "r"(a0), "r"(a1), "r"(a2), "r"(a3), "r"(b0), "r"(b1));
}

// ---------------------------------------------------------------------------
// One-shot pack of both weight matrices.
// Bf1 ordering: J (0..47) = w*6 + j, gate = j>>1 (0=i,1=g,2=o), jj = j&1.
//   packed col n = gate*128 + w*16 + jj*8 + (l>>2); orig Wl col = n (+128 if n>=128).
// Bf2 ordering: plain j-tiles (n = j*8 + l>>2).
// ---------------------------------------------------------------------------
__global__ void pack_all(const float* __restrict__ Wl, const float* __restrict__ W2,
                         float2* __restrict__ Bf1, float2* __restrict__ Bf2)
{
    int idx = blockIdx.x * 256 + threadIdx.x;
    if (idx < 16 * 48 * 32) {
        int t = idx / (48 * 32);
        int rem = idx % (48 * 32);
        int J = rem >> 5, l = rem & 31;
        int w = J / 6, j = J % 6;
        int gate = j >> 1, jj = j & 1;
        int n = gate * 128 + w * 16 + jj * 8 + (l >> 2);
        int col = n + ((n >= 128) ? 128 : 0);
        int k = t * 8 + (l & 3);
        float2 o;
        o.x = __uint_as_float(f2tf32(Wl[(size_t)k * 512 + col]));
        o.y = __uint_as_float(f2tf32(Wl[(size_t)(k + 4) * 512 + col]));
        Bf1[idx] = o;
    } else {
        int i2 = idx - 16 * 48 * 32;   // < 32*16*32
        int t = i2 / (16 * 32);
        int rem = i2 % (16 * 32);
        int j = rem >> 5, l = rem & 31;
        int n = j * 8 + (l >> 2);
        int k = t * 8 + (l & 3);
        float2 o;
        o.x = __uint_as_float(f2tf32(W2[(size_t)k * 128 + n]));
        o.y = __uint_as_float(f2tf32(W2[(size_t)(k + 4) * 128 + n]));
        Bf2[i2] = o;
    }
}

// ---------------------------------------------------------------------------
// Fused encoder: per CTA = 16 rows, 256 threads (8 warps).
//   B: z = x @ Wl (tf32 mma; warp w owns i/g/o cols for u in [16w,16w+16))
//      -> gates in registers -> query [h,c] to smem (no z tile!)
//   C: s2 = query @ W2 (+b2+w1b) -> smem
//   D: e_n = sum_k tanh(x_n*w1_k + base_k)*v_k; softmax; out = x*alpha
// ---------------------------------------------------------------------------
#define XS  132
#define QS  260
#define SS  132

#define OFF_X   0
#define OFF_Q   (16 * XS)              // 2112
#define OFF_S2  (OFF_Q + 16 * QS)      // 6272
#define OFF_WV  (OFF_S2 + 16 * SS)     // 8384
#define OFF_BL  (OFF_WV + 256)         // 8640
#define OFF_BB  (OFF_BL + 384)         // 9024
#define SMEM_FLOATS (OFF_BB + 128)     // 9152 -> 36608 bytes

__global__ void __launch_bounds__(256)
fused_enc(const float* __restrict__ x,
          const float2* __restrict__ Bf1, const float2* __restrict__ Bf2,
          const float* __restrict__ bl,  const float* __restrict__ b2,
          const float* __restrict__ w1,  const float* __restrict__ w1b,
          const float* __restrict__ v,   float* __restrict__ out)
{
    extern __shared__ float sm[];
    float*  X   = sm + OFF_X;
    float*  Q   = sm + OFF_Q;
    float*  S2  = sm + OFF_S2;
    float2* WV  = reinterpret_cast<float2*>(sm + OFF_WV);
    float*  BLs = sm + OFF_BL;
    float*  BB  = sm + OFF_BB;

    const int tid  = threadIdx.x;
    const int lane = tid & 31;
    const int w    = tid >> 5;          // 0..7
    const int r0   = blockIdx.x * 16;

    // ---- load x strip + broadcast vectors ----
    #pragma unroll
    for (int it = 0; it < 2; ++it) {
        int i = it * 256 + tid;          // < 512
        int row = i >> 5, q4 = i & 31;
        float4 vv = *reinterpret_cast<const float4*>(
            x + (size_t)(r0 + row) * 128 + q4 * 4);
        *reinterpret_cast<float4*>(&X[row * XS + q4 * 4]) = vv;
    }
    if (tid < 128) {
        WV[tid] = make_float2(w1[tid], v[tid]);
        BLs[tid]       = bl[tid];          // i bias
        BLs[128 + tid] = bl[256 + tid];    // g bias
        BLs[256 + tid] = bl[384 + tid];    // o bias
        BB[tid] = b2[tid] + w1b[tid];
    }
    __syncthreads();

    // ---- Phase B: z GEMM + in-register gates -> Q ----
    {
        float acc[6][4];
        #pragma unroll
        for (int j = 0; j < 6; ++j)
            #pragma unroll
            for (int e = 0; e < 4; ++e) acc[j][e] = 0.f;

        const int arow = lane >> 2, acol0 = lane & 3;
        #pragma unroll
        for (int t = 0; t < 16; ++t) {
            int ac = acol0 + t * 8;
            uint32_t a0 = f2tf32(X[arow * XS + ac]);
            uint32_t a1 = f2tf32(X[(arow + 8) * XS + ac]);
            uint32_t a2 = f2tf32(X[arow * XS + ac + 4]);
            uint32_t a3 = f2tf32(X[(arow + 8) * XS + ac + 4]);
            const float2* bp = Bf1 + (size_t)(t * 48 + w * 6) * 32 + lane;
            #pragma unroll
            for (int j = 0; j < 6; ++j) {
                float2 b = bp[j * 32];
                mma_tf32(acc[j], a0, a1, a2, a3,
                         __float_as_uint(b.x), __float_as_uint(b.y));
            }
        }

        // gates from registers: acc[jj]=i, acc[2+jj]=g, acc[4+jj]=o
        const int crow = lane >> 2, cc = 2 * (lane & 3);
        #pragma unroll
        for (int jj = 0; jj < 2; ++jj) {
            const int u0 = w * 16 + jj * 8 + cc;    // two cols: u0, u0+1
            const float bi0 = BLs[u0],       bi1 = BLs[u0 + 1];
            const float bg0 = BLs[128 + u0], bg1 = BLs[128 + u0 + 1];
            const float bo0 = BLs[256 + u0], bo1 = BLs[256 + u0 + 1];
            #pragma unroll
            for (int half = 0; half < 2; ++half) {
                const int row = crow + 8 * half;
                float iv0 = acc[jj][2*half]     + bi0;
                float iv1 = acc[jj][2*half + 1] + bi1;
                float gv0 = acc[2+jj][2*half]     + bg0;
                float gv1 = acc[2+jj][2*half + 1] + bg1;
                float ov0 = acc[4+jj][2*half]     + bo0;
                float ov1 = acc[4+jj][2*half + 1] + bo1;
                float c0 = (0.5f * tanh_fast(0.5f * iv0) + 0.5f) * tanh_fast(gv0);
                float c1 = (0.5f * tanh_fast(0.5f * iv1) + 0.5f) * tanh_fast(gv1);
                float h0 = (0.5f * tanh_fast(0.5f * ov0) + 0.5f) * tanh_fast(c0);
                float h1 = (0.5f * tanh_fast(0.5f * ov1) + 0.5f) * tanh_fast(c1);
                *reinterpret_cast<float2*>(&Q[row * QS + u0])       = make_float2(h0, h1);
                *reinterpret_cast<float2*>(&Q[row * QS + 128 + u0]) = make_float2(c0, c1);
            }
        }
    }
    __syncthreads();

    // ---- Phase C: s2 GEMM (16 x 128, K=256). warp w -> cols [w*16, w*16+16) ----
    {
        float acc[2][4];
        #pragma unroll
        for (int j = 0; j < 2; ++j)
            #pragma unroll
            for (int e = 0; e < 4; ++e) acc[j][e] = 0.f;

        const int arow = lane >> 2, acol0 = lane & 3;
        #pragma unroll
        for (int t = 0; t < 32; ++t) {
            int ac = acol0 + t * 8;
            uint32_t a0 = f2tf32(Q[arow * QS + ac]);
            uint32_t a1 = f2tf32(Q[(arow + 8) * QS + ac]);
            uint32_t a2 = f2tf32(Q[arow * QS + ac + 4]);
            uint32_t a3 = f2tf32(Q[(arow + 8) * QS + ac + 4]);
            const float2* bp = Bf2 + (size_t)(t * 16 + w * 2) * 32 + lane;
            #pragma unroll
            for (int j = 0; j < 2; ++j) {
                float2 b = bp[j * 32];
                mma_tf32(acc[j], a0, a1, a2, a3,
                         __float_as_uint(b.x), __float_as_uint(b.y));
            }
        }
        const int crow = lane >> 2, cc = 2 * (lane & 3);
        #pragma unroll
        for (int j = 0; j < 2; ++j) {
            int col = w * 16 + j * 8 + cc;
            float bb0 = BB[col], bb1 = BB[col + 1];
            *reinterpret_cast<float2*>(&S2[crow * SS + col]) =
                make_float2(acc[j][0] + bb0, acc[j][1] + bb1);
            *reinterpret_cast<float2*>(&S2[(crow + 8) * SS + col]) =
                make_float2(acc[j][2] + bb0, acc[j][3] + bb1);
        }
    }
    __syncthreads();

    // ---- Phase D: attention. thread -> (row = tid/16, 8 n's strided by 16) ----
    {
        const int row = tid >> 4;
        const int nb  = tid & 15;
        const float* xr = &X[row * XS + nb];
        const float* br = &S2[row * SS];

        float xv[8], ea[8];
        #pragma unroll
        for (int j = 0; j < 8; ++j) { xv[j] = xr[16 * j]; ea[j] = 0.f; }

        #pragma unroll 4
        for (int k = 0; k < 128; ++k) {
            float2 wv = WV[k];
            float  bb = br[k];
            #pragma unroll
            for (int j = 0; j < 8; ++j)
                ea[j] = fmaf(tanh_fast(fmaf(xv[j], wv.x, bb)), wv.y, ea[j]);
        }

        float m = ea[0];
        #pragma unroll
        for (int j = 1; j < 8; ++j) m = fmaxf(m, ea[j]);
        #pragma unroll
        for (int o = 8; o > 0; o >>= 1)
            m = fmaxf(m, __shfl_xor_sync(0xffffffffu, m, o));

        float p[8], s = 0.f;
        #pragma unroll
        for (int j = 0; j < 8; ++j) { p[j] = __expf(ea[j] - m); s += p[j]; }
        #pragma unroll
        for (int o = 8; o > 0; o >>= 1)
            s += __shfl_xor_sync(0xffffffffu, s, o);
        float inv = 1.f / s;

        float* orow = out + (size_t)(r0 + row) * 128 + nb;
        #pragma unroll
        for (int j = 0; j < 8; ++j)
            orow[16 * j] = xv[j] * p[j] * inv;
    }
}

// ---------------------------------------------------------------------------
extern "C" void kernel_launch(void* const* d_in, const int* in_sizes, int n_in,
                              void* d_out, int out_size)
{
    const float* x   = (const float*)d_in[0];
    const float* Wl  = (const float*)d_in[3];   // (128, 512)
    const float* bl  = (const float*)d_in[4];   // (512)
    const float* w1  = (const float*)d_in[5];   // (128)
    const float* w1b = (const float*)d_in[6];   // (128)
    const float* W2  = (const float*)d_in[7];   // (256, 128)
    const float* b2  = (const float*)d_in[8];   // (128)
    const float* v   = (const float*)d_in[9];   // (128)
    float* out = (float*)d_out;

    float2 *bf1, *bf2;
    cudaGetSymbolAddress((void**)&bf1, g_Bf1);
    cudaGetSymbolAddress((void**)&bf2, g_Bf2);

    static int smem_set = 0;
    if (!smem_set) {
        cudaFuncSetAttribute(fused_enc,
            cudaFuncAttributeMaxDynamicSharedMemorySize, SMEM_FLOATS * 4);
        smem_set = 1;
    }

    pack_all<<<160, 256>>>(Wl, W2, bf1, bf2);   // 40960 threads
    fused_enc<<<ROWS / 16, 256, SMEM_FLOATS * 4>>>(
        x, bf1, bf2, bl, b2, w1, w1b, v, out);
}

// round 7
// speedup vs baseline: 3.3125x; 1.7007x over previous
#include <cuda_runtime.h>
#include <cstdint>
#include <math.h>

// Problem constants: B=64, T=128, N=128, U=128
#define ROWS 8192   // B*T

// Prepacked weight fragments (device globals -- no allocations allowed)
__device__ float2 g_Bf1[16 * 48 * 32];   // Wl packed (K=128, N=384, gate-interleaved)
__device__ float2 g_Bf2[32 * 16 * 32];   // W2 packed (K=256, N=128)

// ---------------------------------------------------------------------------
// helpers
// ---------------------------------------------------------------------------
__device__ __forceinline__ float tanh_fast(float x) {
    float y;
    asm("tanh.approx.f32 %0, %1;" : "=f"(y) : "f"(x));
    return y;
}
__device__ __forceinline__ uint32_t f2tf32(float f) {
    uint32_t u;
    asm("cvt.rna.tf32.f32 %0, %1;" : "=r"(u) : "f"(f));
    return u;
}
__device__ __forceinline__ void mma_tf32(float c[4], uint32_t a0, uint32_t a1,
                                         uint32_t a2, uint32_t a3,
                                         uint32_t b0, uint32_t b1) {
    asm volatile(
        "mma.sync.aligned.m16n8k8.row.col.f32.tf32.tf32.f32 "
        "{%0,%1,%2,%3}, {%4,%5,%6,%7}, {%8,%9}, {%0,%1,%2,%3};"
        : "+f"(c[0]), "+f"(c[1]), "+f"(c[2]), "+f"(c[3])
        : "r"(a0), "r"(a1), "r"(a2), "r"(a3), "r"(b0), "r"(b1));
}

// ---------------------------------------------------------------------------
// One-shot pack of both weight matrices (gate-interleaved Bf1; see round 4).
// ---------------------------------------------------------------------------
__global__ void pack_all(const float* __restrict__ Wl, const float* __restrict__ W2,
                         float2* __restrict__ Bf1, float2* __restrict__ Bf2)
{
    int idx = blockIdx.x * 256 + threadIdx.x;
    if (idx < 16 * 48 * 32) {
        int t = idx / (48 * 32);
        int rem = idx % (48 * 32);
        int J = rem >> 5, l = rem & 31;
        int w = J / 6, j = J % 6;
        int gate = j >> 1, jj = j & 1;
        int n = gate * 128 + w * 16 + jj * 8 + (l >> 2);
        int col = n + ((n >= 128) ? 128 : 0);
        int k = t * 8 + (l & 3);
        float2 o;
        o.x = __uint_as_float(f2tf32(Wl[(size_t)k * 512 + col]));
        o.y = __uint_as_float(f2tf32(Wl[(size_t)(k + 4) * 512 + col]));
        Bf1[idx] = o;
    } else {
        int i2 = idx - 16 * 48 * 32;   // < 32*16*32
        int t = i2 / (16 * 32);
        int rem = i2 % (16 * 32);
        int j = rem >> 5, l = rem & 31;
        int n = j * 8 + (l >> 2);
        int k = t * 8 + (l & 3);
        float2 o;
        o.x = __uint_as_float(f2tf32(W2[(size_t)k * 128 + n]));
        o.y = __uint_as_float(f2tf32(W2[(size_t)(k + 4) * 128 + n]));
        Bf2[i2] = o;
    }
}

// ---------------------------------------------------------------------------
// Fused encoder: per CTA = 16 rows, 256 threads (8 warps).
//   B: z GEMM (tf32 mma) -> gates in registers -> Q = [h,c] in smem
//   C: s2 GEMM -> S2 (= s2 + b2 + w1b) in smem
//   D: per row, e(x) = sum_k v_k tanh(w1_k x + S2_k) is a smooth scalar fn:
//      sample at 16 Chebyshev nodes on [-8,8] (16 rows x 16 nodes = 256 thr),
//      DCT -> Chebyshev coeffs, Clenshaw-eval per n, softmax, out = x*alpha.
// ---------------------------------------------------------------------------
#define XS  132
#define QS  260
#define SS  132

#define OFF_X   0
#define OFF_Q   (16 * XS)              // 2112
#define OFF_S2  (OFF_Q + 16 * QS)      // 6272
#define OFF_WV  (OFF_S2 + 16 * SS)     // 8384
#define OFF_BL  (OFF_WV + 256)         // 8640
#define OFF_BB  (OFF_BL + 384)         // 9024
#define OFF_CM  (OFF_BB + 128)         // 9152  (CMT[j][m] = cos(m*th_j), 16x16)
#define OFF_F   (OFF_CM + 256)         // 9408  (node values, 16x16)
#define OFF_AC  (OFF_F + 256)          // 9664  (cheb coeffs, 16x16)
#define SMEM_FLOATS (OFF_AC + 256)     // 9920 -> 39680 bytes (static)

__global__ void __launch_bounds__(256)
fused_enc(const float* __restrict__ x,
          const float2* __restrict__ Bf1, const float2* __restrict__ Bf2,
          const float* __restrict__ bl,  const float* __restrict__ b2,
          const float* __restrict__ w1,  const float* __restrict__ w1b,
          const float* __restrict__ v,   float* __restrict__ out)
{
    __shared__ float sm[SMEM_FLOATS];
    float*  X   = sm + OFF_X;
    float*  Q   = sm + OFF_Q;
    float*  S2  = sm + OFF_S2;
    float2* WV  = reinterpret_cast<float2*>(sm + OFF_WV);
    float*  BLs = sm + OFF_BL;
    float*  BB  = sm + OFF_BB;
    float*  CMT = sm + OFF_CM;
    float*  F   = sm + OFF_F;
    float*  ACF = sm + OFF_AC;

    const int tid  = threadIdx.x;
    const int lane = tid & 31;
    const int w    = tid >> 5;          // 0..7
    const int r0   = blockIdx.x * 16;

    // ---- load x strip + broadcast vectors + DCT matrix ----
    #pragma unroll
    for (int it = 0; it < 2; ++it) {
        int i = it * 256 + tid;          // < 512
        int row = i >> 5, q4 = i & 31;
        float4 vv = *reinterpret_cast<const float4*>(
            x + (size_t)(r0 + row) * 128 + q4 * 4);
        *reinterpret_cast<float4*>(&X[row * XS + q4 * 4]) = vv;
    }
    {   // CMT[j*16+m] = cos(m*(2j+1)*pi/32)
        int j = tid >> 4, m = tid & 15;
        CMT[tid] = cospif((float)(m * (2 * j + 1)) / 32.0f);
    }
    if (tid < 128) {
        WV[tid] = make_float2(w1[tid], v[tid]);
        BLs[tid]       = bl[tid];          // i bias
        BLs[128 + tid] = bl[256 + tid];    // g bias
        BLs[256 + tid] = bl[384 + tid];    // o bias
        BB[tid] = b2[tid] + w1b[tid];
    }
    __syncthreads();

    // ---- Phase B: z GEMM + in-register gates -> Q ----
    {
        float acc[6][4];
        #pragma unroll
        for (int j = 0; j < 6; ++j)
            #pragma unroll
            for (int e = 0; e < 4; ++e) acc[j][e] = 0.f;

        const int arow = lane >> 2, acol0 = lane & 3;
        #pragma unroll
        for (int t = 0; t < 16; ++t) {
            int ac = acol0 + t * 8;
            uint32_t a0 = f2tf32(X[arow * XS + ac]);
            uint32_t a1 = f2tf32(X[(arow + 8) * XS + ac]);
            uint32_t a2 = f2tf32(X[arow * XS + ac + 4]);
            uint32_t a3 = f2tf32(X[(arow + 8) * XS + ac + 4]);
            const float2* bp = Bf1 + (size_t)(t * 48 + w * 6) * 32 + lane;
            #pragma unroll
            for (int j = 0; j < 6; ++j) {
                float2 b = bp[j * 32];
                mma_tf32(acc[j], a0, a1, a2, a3,
                         __float_as_uint(b.x), __float_as_uint(b.y));
            }
        }

        const int crow = lane >> 2, cc = 2 * (lane & 3);
        #pragma unroll
        for (int jj = 0; jj < 2; ++jj) {
            const int u0 = w * 16 + jj * 8 + cc;
            const float bi0 = BLs[u0],       bi1 = BLs[u0 + 1];
            const float bg0 = BLs[128 + u0], bg1 = BLs[128 + u0 + 1];
            const float bo0 = BLs[256 + u0], bo1 = BLs[256 + u0 + 1];
            #pragma unroll
            for (int half = 0; half < 2; ++half) {
                const int row = crow + 8 * half;
                float iv0 = acc[jj][2*half]       + bi0;
                float iv1 = acc[jj][2*half + 1]   + bi1;
                float gv0 = acc[2+jj][2*half]     + bg0;
                float gv1 = acc[2+jj][2*half + 1] + bg1;
                float ov0 = acc[4+jj][2*half]     + bo0;
                float ov1 = acc[4+jj][2*half + 1] + bo1;
                float c0 = (0.5f * tanh_fast(0.5f * iv0) + 0.5f) * tanh_fast(gv0);
                float c1 = (0.5f * tanh_fast(0.5f * iv1) + 0.5f) * tanh_fast(gv1);
                float h0 = (0.5f * tanh_fast(0.5f * ov0) + 0.5f) * tanh_fast(c0);
                float h1 = (0.5f * tanh_fast(0.5f * ov1) + 0.5f) * tanh_fast(c1);
                *reinterpret_cast<float2*>(&Q[row * QS + u0])       = make_float2(h0, h1);
                *reinterpret_cast<float2*>(&Q[row * QS + 128 + u0]) = make_float2(c0, c1);
            }
        }
    }
    __syncthreads();

    // ---- Phase C: s2 GEMM (16 x 128, K=256) -> S2 = s2 + b2 + w1b ----
    {
        float acc[2][4];
        #pragma unroll
        for (int j = 0; j < 2; ++j)
            #pragma unroll
            for (int e = 0; e < 4; ++e) acc[j][e] = 0.f;

        const int arow = lane >> 2, acol0 = lane & 3;
        #pragma unroll
        for (int t = 0; t < 32; ++t) {
            int ac = acol0 + t * 8;
            uint32_t a0 = f2tf32(Q[arow * QS + ac]);
            uint32_t a1 = f2tf32(Q[(arow + 8) * QS + ac]);
            uint32_t a2 = f2tf32(Q[arow * QS + ac + 4]);
            uint32_t a3 = f2tf32(Q[(arow + 8) * QS + ac + 4]);
            const float2* bp = Bf2 + (size_t)(t * 16 + w * 2) * 32 + lane;
            #pragma unroll
            for (int j = 0; j < 2; ++j) {
                float2 b = bp[j * 32];
                mma_tf32(acc[j], a0, a1, a2, a3,
                         __float_as_uint(b.x), __float_as_uint(b.y));
            }
        }
        const int crow = lane >> 2, cc = 2 * (lane & 3);
        #pragma unroll
        for (int j = 0; j < 2; ++j) {
            int col = w * 16 + j * 8 + cc;
            float bb0 = BB[col], bb1 = BB[col + 1];
            *reinterpret_cast<float2*>(&S2[crow * SS + col]) =
                make_float2(acc[j][0] + bb0, acc[j][1] + bb1);
            *reinterpret_cast<float2*>(&S2[(crow + 8) * SS + col]) =
                make_float2(acc[j][2] + bb0, acc[j][3] + bb1);
        }
    }
    __syncthreads();

    // ---- Phase D1: node evaluation. thread = (row = tid/16, node j = tid%16)
    //      f_row(t_j) = sum_k v_k * tanh(w1_k * t_j + S2[row][k])
    {
        const int row = tid >> 4;
        const int j   = tid & 15;
        const float tj = 8.0f * CMT[j * 16 + 1];   // node = 8*cos(th_j)
        const float* br = &S2[row * SS];

        float f0 = 0.f, f1 = 0.f, f2 = 0.f, f3 = 0.f;
        #pragma unroll 8
        for (int k = 0; k < 128; k += 4) {
            float2 wv0 = WV[k+0]; float b0 = br[k+0];
            float2 wv1 = WV[k+1]; float b1 = br[k+1];
            float2 wv2 = WV[k+2]; float b2v = br[k+2];
            float2 wv3 = WV[k+3]; float b3 = br[k+3];
            f0 = fmaf(tanh_fast(fmaf(wv0.x, tj, b0)),  wv0.y, f0);
            f1 = fmaf(tanh_fast(fmaf(wv1.x, tj, b1)),  wv1.y, f1);
            f2 = fmaf(tanh_fast(fmaf(wv2.x, tj, b2v)), wv2.y, f2);
            f3 = fmaf(tanh_fast(fmaf(wv3.x, tj, b3)),  wv3.y, f3);
        }
        F[row * 16 + j] = (f0 + f1) + (f2 + f3);
    }
    __syncthreads();

    // ---- Phase D2: Chebyshev coefficients. thread = (row, m)
    {
        const int row = tid >> 4;
        const int m   = tid & 15;
        float acc = 0.f;
        #pragma unroll
        for (int j = 0; j < 16; ++j)
            acc = fmaf(F[row * 16 + j], CMT[j * 16 + m], acc);
        ACF[row * 16 + m] = acc * ((m == 0) ? 0.0625f : 0.125f);
    }
    __syncthreads();

    // ---- Phase D3: Clenshaw eval + softmax + output.
    //      thread = (row = tid/16, nb = tid%16), 8 n's strided by 16.
    {
        const int row = tid >> 4;
        const int nb  = tid & 15;
        const float* xr = &X[row * XS + nb];

        float a[16];
        #pragma unroll
        for (int m = 0; m < 16; ++m) a[m] = ACF[row * 16 + m];

        float xv[8], ea[8];
        #pragma unroll
        for (int j = 0; j < 8; ++j) xv[j] = xr[16 * j];

        #pragma unroll
        for (int j = 0; j < 8; ++j) {
            float t  = xv[j] * 0.125f;
            float tt = t + t;
            float c1 = a[15], c2 = 0.f;
            #pragma unroll
            for (int m = 14; m >= 1; --m) {
                float cn = fmaf(tt, c1, a[m] - c2);
                c2 = c1; c1 = cn;
            }
            ea[j] = fmaf(t, c1, a[0] - c2);
        }

        // softmax over the row's 128 n's (16 lanes x 8 regs)
        float m = ea[0];
        #pragma unroll
        for (int j = 1; j < 8; ++j) m = fmaxf(m, ea[j]);
        #pragma unroll
        for (int o = 8; o > 0; o >>= 1)
            m = fmaxf(m, __shfl_xor_sync(0xffffffffu, m, o));

        float p[8], s = 0.f;
        #pragma unroll
        for (int j = 0; j < 8; ++j) { p[j] = __expf(ea[j] - m); s += p[j]; }
        #pragma unroll
        for (int o = 8; o > 0; o >>= 1)
            s += __shfl_xor_sync(0xffffffffu, s, o);
        float inv = 1.f / s;

        float* orow = out + (size_t)(r0 + row) * 128 + nb;
        #pragma unroll
        for (int j = 0; j < 8; ++j)
            orow[16 * j] = xv[j] * p[j] * inv;
    }
}

// ---------------------------------------------------------------------------
extern "C" void kernel_launch(void* const* d_in, const int* in_sizes, int n_in,
                              void* d_out, int out_size)
{
    const float* x   = (const float*)d_in[0];
    const float* Wl  = (const float*)d_in[3];   // (128, 512)
    const float* bl  = (const float*)d_in[4];   // (512)
    const float* w1  = (const float*)d_in[5];   // (128)
    const float* w1b = (const float*)d_in[6];   // (128)
    const float* W2  = (const float*)d_in[7];   // (256, 128)
    const float* b2  = (const float*)d_in[8];   // (128)
    const float* v   = (const float*)d_in[9];   // (128)
    float* out = (float*)d_out;

    float2 *bf1, *bf2;
    cudaGetSymbolAddress((void**)&bf1, g_Bf1);
    cudaGetSymbolAddress((void**)&bf2, g_Bf2);

    pack_all<<<160, 256>>>(Wl, W2, bf1, bf2);   // 40960 threads
    fused_enc<<<ROWS / 16, 256>>>(x, bf1, bf2, bl, b2, w1, w1b, v, out);
}

// round 8
// speedup vs baseline: 3.4291x; 1.0352x over previous
#include <cuda_runtime.h>
#include <cstdint>
#include <math.h>

// Problem constants: B=64, T=128, N=128, U=128
#define ROWS 8192   // B*T

// Prepacked weight fragments (device globals -- no allocations allowed)
__device__ float2 g_Bf1[16 * 48 * 32];   // Wl packed (K=128, N=384, gate-interleaved)
__device__ float2 g_Bf2[32 * 16 * 32];   // W2 packed (K=256, N=128)

// ---------------------------------------------------------------------------
// helpers
// ---------------------------------------------------------------------------
__device__ __forceinline__ float tanh_fast(float x) {
    float y;
    asm("tanh.approx.f32 %0, %1;" : "=f"(y) : "f"(x));
    return y;
}
__device__ __forceinline__ uint32_t f2tf32(float f) {
    uint32_t u;
    asm("cvt.rna.tf32.f32 %0, %1;" : "=r"(u) : "f"(f));
    return u;
}
__device__ __forceinline__ void mma_tf32(float c[4], uint32_t a0, uint32_t a1,
                                         uint32_t a2, uint32_t a3,
                                         uint32_t b0, uint32_t b1) {
    asm volatile(
        "mma.sync.aligned.m16n8k8.row.col.f32.tf32.tf32.f32 "
        "{%0,%1,%2,%3}, {%4,%5,%6,%7}, {%8,%9}, {%0,%1,%2,%3};"
        : "+f"(c[0]), "+f"(c[1]), "+f"(c[2]), "+f"(c[3])
        : "r"(a0), "r"(a1), "r"(a2), "r"(a3), "r"(b0), "r"(b1));
}

// ---------------------------------------------------------------------------
// One-shot pack of both weight matrices (gate-interleaved Bf1; see round 4).
// ---------------------------------------------------------------------------
__global__ void pack_all(const float* __restrict__ Wl, const float* __restrict__ W2,
                         float2* __restrict__ Bf1, float2* __restrict__ Bf2)
{
    int idx = blockIdx.x * 256 + threadIdx.x;
    if (idx < 16 * 48 * 32) {
        int t = idx / (48 * 32);
        int rem = idx % (48 * 32);
        int J = rem >> 5, l = rem & 31;
        int w = J / 6, j = J % 6;
        int gate = j >> 1, jj = j & 1;
        int n = gate * 128 + w * 16 + jj * 8 + (l >> 2);
        int col = n + ((n >= 128) ? 128 : 0);
        int k = t * 8 + (l & 3);
        float2 o;
        o.x = __uint_as_float(f2tf32(Wl[(size_t)k * 512 + col]));
        o.y = __uint_as_float(f2tf32(Wl[(size_t)(k + 4) * 512 + col]));
        Bf1[idx] = o;
    } else {
        int i2 = idx - 16 * 48 * 32;   // < 32*16*32
        int t = i2 / (16 * 32);
        int rem = i2 % (16 * 32);
        int j = rem >> 5, l = rem & 31;
        int n = j * 8 + (l >> 2);
        int k = t * 8 + (l & 3);
        float2 o;
        o.x = __uint_as_float(f2tf32(W2[(size_t)k * 128 + n]));
        o.y = __uint_as_float(f2tf32(W2[(size_t)(k + 4) * 128 + n]));
        Bf2[i2] = o;
    }
}

// ---------------------------------------------------------------------------
// Fused encoder: per CTA = 32 rows (two 16-row M-tiles/warp), 256 threads.
//   B: z GEMM (tf32 mma, B-frags reused across both M-tiles)
//      -> gates in registers -> Q = [h,c] in smem
//   C: s2 GEMM -> S2 (= s2 + b2 + w1b) in smem
//   D: per row, e(x) = sum_k v_k tanh(w1_k x + S2_k): sample at 16 Chebyshev
//      nodes, DCT -> coeffs, Clenshaw per n, softmax, out = x*alpha.
//      (2 passes of 16 rows.)
// ---------------------------------------------------------------------------
#define XS  132
#define QS  260
#define SS  132

#define OFF_X   0
#define OFF_Q   (32 * XS)              // 4224
#define OFF_S2  (OFF_Q + 32 * QS)      // 12544
#define OFF_WV  (OFF_S2 + 32 * SS)     // 16768
#define OFF_BL  (OFF_WV + 256)         // 17024
#define OFF_BB  (OFF_BL + 384)         // 17408
#define OFF_CM  (OFF_BB + 128)         // 17536
#define OFF_F   (OFF_CM + 256)         // 17792  (node values, 32x16)
#define OFF_AC  (OFF_F + 512)          // 18304  (cheb coeffs, 32x16)
#define SMEM_FLOATS (OFF_AC + 512)     // 18816 -> 75264 bytes (dynamic)

__global__ void __launch_bounds__(256)
fused_enc(const float* __restrict__ x,
          const float2* __restrict__ Bf1, const float2* __restrict__ Bf2,
          const float* __restrict__ bl,  const float* __restrict__ b2,
          const float* __restrict__ w1,  const float* __restrict__ w1b,
          const float* __restrict__ v,   float* __restrict__ out)
{
    extern __shared__ float sm[];
    float*  X   = sm + OFF_X;
    float*  Q   = sm + OFF_Q;
    float*  S2  = sm + OFF_S2;
    float2* WV  = reinterpret_cast<float2*>(sm + OFF_WV);
    float*  BLs = sm + OFF_BL;
    float*  BB  = sm + OFF_BB;
    float*  CMT = sm + OFF_CM;
    float*  F   = sm + OFF_F;
    float*  ACF = sm + OFF_AC;

    const int tid  = threadIdx.x;
    const int lane = tid & 31;
    const int w    = tid >> 5;          // 0..7
    const int r0   = blockIdx.x * 32;

    // ---- load x strip (32 x 128) + broadcast vectors + DCT matrix ----
    #pragma unroll
    for (int it = 0; it < 4; ++it) {
        int i = it * 256 + tid;          // < 1024
        int row = i >> 5, q4 = i & 31;
        float4 vv = *reinterpret_cast<const float4*>(
            x + (size_t)(r0 + row) * 128 + q4 * 4);
        *reinterpret_cast<float4*>(&X[row * XS + q4 * 4]) = vv;
    }
    {   // CMT[j*16+m] = cos(m*(2j+1)*pi/32)
        int j = tid >> 4, m = tid & 15;
        CMT[tid] = cospif((float)(m * (2 * j + 1)) / 32.0f);
    }
    if (tid < 128) {
        WV[tid] = make_float2(w1[tid], v[tid]);
        BLs[tid]       = bl[tid];          // i bias
        BLs[128 + tid] = bl[256 + tid];    // g bias
        BLs[256 + tid] = bl[384 + tid];    // o bias
        BB[tid] = b2[tid] + w1b[tid];
    }
    __syncthreads();

    // ---- Phase B: z GEMM (2 M-tiles) + in-register gates -> Q ----
    {
        float acc[2][6][4];
        #pragma unroll
        for (int mtile = 0; mtile < 2; ++mtile)
            #pragma unroll
            for (int j = 0; j < 6; ++j)
                #pragma unroll
                for (int e = 0; e < 4; ++e) acc[mtile][j][e] = 0.f;

        const int arow = lane >> 2, acol0 = lane & 3;
        #pragma unroll
        for (int t = 0; t < 16; ++t) {
            int ac = acol0 + t * 8;
            uint32_t a00 = f2tf32(X[arow * XS + ac]);
            uint32_t a01 = f2tf32(X[(arow + 8) * XS + ac]);
            uint32_t a02 = f2tf32(X[arow * XS + ac + 4]);
            uint32_t a03 = f2tf32(X[(arow + 8) * XS + ac + 4]);
            uint32_t a10 = f2tf32(X[(arow + 16) * XS + ac]);
            uint32_t a11 = f2tf32(X[(arow + 24) * XS + ac]);
            uint32_t a12 = f2tf32(X[(arow + 16) * XS + ac + 4]);
            uint32_t a13 = f2tf32(X[(arow + 24) * XS + ac + 4]);
            const float2* bp = Bf1 + (size_t)(t * 48 + w * 6) * 32 + lane;
            #pragma unroll
            for (int j = 0; j < 6; ++j) {
                float2 b = bp[j * 32];
                uint32_t bx = __float_as_uint(b.x), by = __float_as_uint(b.y);
                mma_tf32(acc[0][j], a00, a01, a02, a03, bx, by);
                mma_tf32(acc[1][j], a10, a11, a12, a13, bx, by);
            }
        }

        const int crow = lane >> 2, cc = 2 * (lane & 3);
        #pragma unroll
        for (int mtile = 0; mtile < 2; ++mtile) {
            #pragma unroll
            for (int jj = 0; jj < 2; ++jj) {
                const int u0 = w * 16 + jj * 8 + cc;
                const float bi0 = BLs[u0],       bi1 = BLs[u0 + 1];
                const float bg0 = BLs[128 + u0], bg1 = BLs[128 + u0 + 1];
                const float bo0 = BLs[256 + u0], bo1 = BLs[256 + u0 + 1];
                #pragma unroll
                for (int half = 0; half < 2; ++half) {
                    const int row = mtile * 16 + crow + 8 * half;
                    float iv0 = acc[mtile][jj][2*half]       + bi0;
                    float iv1 = acc[mtile][jj][2*half + 1]   + bi1;
                    float gv0 = acc[mtile][2+jj][2*half]     + bg0;
                    float gv1 = acc[mtile][2+jj][2*half + 1] + bg1;
                    float ov0 = acc[mtile][4+jj][2*half]     + bo0;
                    float ov1 = acc[mtile][4+jj][2*half + 1] + bo1;
                    float c0 = (0.5f * tanh_fast(0.5f * iv0) + 0.5f) * tanh_fast(gv0);
                    float c1 = (0.5f * tanh_fast(0.5f * iv1) + 0.5f) * tanh_fast(gv1);
                    float h0 = (0.5f * tanh_fast(0.5f * ov0) + 0.5f) * tanh_fast(c0);
                    float h1 = (0.5f * tanh_fast(0.5f * ov1) + 0.5f) * tanh_fast(c1);
                    *reinterpret_cast<float2*>(&Q[row * QS + u0])       = make_float2(h0, h1);
                    *reinterpret_cast<float2*>(&Q[row * QS + 128 + u0]) = make_float2(c0, c1);
                }
            }
        }
    }
    __syncthreads();

    // ---- Phase C: s2 GEMM (32 x 128, K=256) -> S2 = s2 + b2 + w1b ----
    {
        float acc[2][2][4];
        #pragma unroll
        for (int mtile = 0; mtile < 2; ++mtile)
            #pragma unroll
            for (int j = 0; j < 2; ++j)
                #pragma unroll
                for (int e = 0; e < 4; ++e) acc[mtile][j][e] = 0.f;

        const int arow = lane >> 2, acol0 = lane & 3;
        #pragma unroll
        for (int t = 0; t < 32; ++t) {
            int ac = acol0 + t * 8;
            uint32_t a00 = f2tf32(Q[arow * QS + ac]);
            uint32_t a01 = f2tf32(Q[(arow + 8) * QS + ac]);
            uint32_t a02 = f2tf32(Q[arow * QS + ac + 4]);
            uint32_t a03 = f2tf32(Q[(arow + 8) * QS + ac + 4]);
            uint32_t a10 = f2tf32(Q[(arow + 16) * QS + ac]);
            uint32_t a11 = f2tf32(Q[(arow + 24) * QS + ac]);
            uint32_t a12 = f2tf32(Q[(arow + 16) * QS + ac + 4]);
            uint32_t a13 = f2tf32(Q[(arow + 24) * QS + ac + 4]);
            const float2* bp = Bf2 + (size_t)(t * 16 + w * 2) * 32 + lane;
            #pragma unroll
            for (int j = 0; j < 2; ++j) {
                float2 b = bp[j * 32];
                uint32_t bx = __float_as_uint(b.x), by = __float_as_uint(b.y);
                mma_tf32(acc[0][j], a00, a01, a02, a03, bx, by);
                mma_tf32(acc[1][j], a10, a11, a12, a13, bx, by);
            }
        }
        const int crow = lane >> 2, cc = 2 * (lane & 3);
        #pragma unroll
        for (int mtile = 0; mtile < 2; ++mtile) {
            #pragma unroll
            for (int j = 0; j < 2; ++j) {
                int col = w * 16 + j * 8 + cc;
                float bb0 = BB[col], bb1 = BB[col + 1];
                int rb = mtile * 16 + crow;
                *reinterpret_cast<float2*>(&S2[rb * SS + col]) =
                    make_float2(acc[mtile][j][0] + bb0, acc[mtile][j][1] + bb1);
                *reinterpret_cast<float2*>(&S2[(rb + 8) * SS + col]) =
                    make_float2(acc[mtile][j][2] + bb0, acc[mtile][j][3] + bb1);
            }
        }
    }
    __syncthreads();

    // ---- Phase D1: node evaluation (2 passes of 16 rows).
    //      thread = (row, node j); f_row(t_j) = sum_k v_k tanh(w1_k t_j + S2_k)
    #pragma unroll
    for (int half = 0; half < 2; ++half) {
        const int row = half * 16 + (tid >> 4);
        const int j   = tid & 15;
        const float tj = 8.0f * CMT[j * 16 + 1];   // node = 8*cos(th_j)
        const float* br = &S2[row * SS];

        float f0 = 0.f, f1 = 0.f, f2 = 0.f, f3 = 0.f;
        #pragma unroll 8
        for (int k = 0; k < 128; k += 4) {
            float2 wv0 = WV[k+0]; float b0 = br[k+0];
            float2 wv1 = WV[k+1]; float b1 = br[k+1];
            float2 wv2 = WV[k+2]; float b2v = br[k+2];
            float2 wv3 = WV[k+3]; float b3 = br[k+3];
            f0 = fmaf(tanh_fast(fmaf(wv0.x, tj, b0)),  wv0.y, f0);
            f1 = fmaf(tanh_fast(fmaf(wv1.x, tj, b1)),  wv1.y, f1);
            f2 = fmaf(tanh_fast(fmaf(wv2.x, tj, b2v)), wv2.y, f2);
            f3 = fmaf(tanh_fast(fmaf(wv3.x, tj, b3)),  wv3.y, f3);
        }
        F[row * 16 + j] = (f0 + f1) + (f2 + f3);
    }
    __syncthreads();

    // ---- Phase D2: Chebyshev coefficients (2 passes). thread = (row, m)
    #pragma unroll
    for (int half = 0; half < 2; ++half) {
        const int row = half * 16 + (tid >> 4);
        const int m   = tid & 15;
        float acc = 0.f;
        #pragma unroll
        for (int j = 0; j < 16; ++j)
            acc = fmaf(F[row * 16 + j], CMT[j * 16 + m], acc);
        ACF[row * 16 + m] = acc * ((m == 0) ? 0.0625f : 0.125f);
    }
    __syncthreads();

    // ---- Phase D3: Clenshaw eval + softmax + output (2 passes).
    //      thread = (row, nb = tid%16), 8 n's strided by 16.
    #pragma unroll
    for (int half = 0; half < 2; ++half) {
        const int row = half * 16 + (tid >> 4);
        const int nb  = tid & 15;
        const float* xr = &X[row * XS + nb];

        float a[16];
        #pragma unroll
        for (int m = 0; m < 16; ++m) a[m] = ACF[row * 16 + m];

        float xv[8], ea[8];
        #pragma unroll
        for (int j = 0; j < 8; ++j) xv[j] = xr[16 * j];

        #pragma unroll
        for (int j = 0; j < 8; ++j) {
            float t  = xv[j] * 0.125f;
            float tt = t + t;
            float c1 = a[15], c2 = 0.f;
            #pragma unroll
            for (int m = 14; m >= 1; --m) {
                float cn = fmaf(tt, c1, a[m] - c2);
                c2 = c1; c1 = cn;
            }
            ea[j] = fmaf(t, c1, a[0] - c2);
        }

        float m = ea[0];
        #pragma unroll
        for (int j = 1; j < 8; ++j) m = fmaxf(m, ea[j]);
        #pragma unroll
        for (int o = 8; o > 0; o >>= 1)
            m = fmaxf(m, __shfl_xor_sync(0xffffffffu, m, o));

        float p[8], s = 0.f;
        #pragma unroll
        for (int j = 0; j < 8; ++j) { p[j] = __expf(ea[j] - m); s += p[j]; }
        #pragma unroll
        for (int o = 8; o > 0; o >>= 1)
            s += __shfl_xor_sync(0xffffffffu, s, o);
        float inv = 1.f / s;

        float* orow = out + (size_t)(r0 + row) * 128 + nb;
        #pragma unroll
        for (int j = 0; j < 8; ++j)
            orow[16 * j] = xv[j] * p[j] * inv;
    }
}

// ---------------------------------------------------------------------------
extern "C" void kernel_launch(void* const* d_in, const int* in_sizes, int n_in,
                              void* d_out, int out_size)
{
    const float* x   = (const float*)d_in[0];
    const float* Wl  = (const float*)d_in[3];   // (128, 512)
    const float* bl  = (const float*)d_in[4];   // (512)
    const float* w1  = (const float*)d_in[5];   // (128)
    const float* w1b = (const float*)d_in[6];   // (128)
    const float* W2  = (const float*)d_in[7];   // (256, 128)
    const float* b2  = (const float*)d_in[8];   // (128)
    const float* v   = (const float*)d_in[9];   // (128)
    float* out = (float*)d_out;

    float2 *bf1, *bf2;
    cudaGetSymbolAddress((void**)&bf1, g_Bf1);
    cudaGetSymbolAddress((void**)&bf2, g_Bf2);

    cudaFuncSetAttribute(fused_enc,
        cudaFuncAttributeMaxDynamicSharedMemorySize, SMEM_FLOATS * 4);

    pack_all<<<160, 256>>>(Wl, W2, bf1, bf2);   // 40960 threads
    fused_enc<<<ROWS / 32, 256, SMEM_FLOATS * 4>>>(
        x, bf1, bf2, bl, b2, w1, w1b, v, out);
}

// round 9
// speedup vs baseline: 3.6050x; 1.0513x over previous
#include <cuda_runtime.h>
#include <cstdint>
#include <math.h>

// Problem constants: B=64, T=128, N=128, U=128
#define ROWS 8192   // B*T

// Prepacked weight fragments (device globals -- no allocations allowed)
__device__ float2 g_Bf1[16 * 48 * 32];   // Wl packed (K=128, N=384, gate-interleaved)
__device__ float2 g_Bf2[32 * 16 * 32];   // W2 packed (K=256, N=128)

// ---------------------------------------------------------------------------
// helpers
// ---------------------------------------------------------------------------
__device__ __forceinline__ float tanh_fast(float x) {
    float y;
    asm("tanh.approx.f32 %0, %1;" : "=f"(y) : "f"(x));
    return y;
}
__device__ __forceinline__ uint32_t f2tf32(float f) {
    uint32_t u;
    asm("cvt.rna.tf32.f32 %0, %1;" : "=r"(u) : "f"(f));
    return u;
}
__device__ __forceinline__ void mma_tf32(float c[4], uint32_t a0, uint32_t a1,
                                         uint32_t a2, uint32_t a3,
                                         uint32_t b0, uint32_t b1) {
    asm volatile(
        "mma.sync.aligned.m16n8k8.row.col.f32.tf32.tf32.f32 "
        "{%0,%1,%2,%3}, {%4,%5,%6,%7}, {%8,%9}, {%0,%1,%2,%3};"
        : "+f"(c[0]), "+f"(c[1]), "+f"(c[2]), "+f"(c[3])
        : "r"(a0), "r"(a1), "r"(a2), "r"(a3), "r"(b0), "r"(b1));
}

// ---------------------------------------------------------------------------
// One-shot pack of both weight matrices (gate-interleaved Bf1; see round 4).
// ---------------------------------------------------------------------------
__global__ void pack_all(const float* __restrict__ Wl, const float* __restrict__ W2,
                         float2* __restrict__ Bf1, float2* __restrict__ Bf2)
{
    int idx = blockIdx.x * 256 + threadIdx.x;
    if (idx < 16 * 48 * 32) {
        int t = idx / (48 * 32);
        int rem = idx % (48 * 32);
        int J = rem >> 5, l = rem & 31;
        int w = J / 6, j = J % 6;
        int gate = j >> 1, jj = j & 1;
        int n = gate * 128 + w * 16 + jj * 8 + (l >> 2);
        int col = n + ((n >= 128) ? 128 : 0);
        int k = t * 8 + (l & 3);
        float2 o;
        o.x = __uint_as_float(f2tf32(Wl[(size_t)k * 512 + col]));
        o.y = __uint_as_float(f2tf32(Wl[(size_t)(k + 4) * 512 + col]));
        Bf1[idx] = o;
    } else {
        int i2 = idx - 16 * 48 * 32;   // < 32*16*32
        int t = i2 / (16 * 32);
        int rem = i2 % (16 * 32);
        int j = rem >> 5, l = rem & 31;
        int n = j * 8 + (l >> 2);
        int k = t * 8 + (l & 3);
        float2 o;
        o.x = __uint_as_float(f2tf32(W2[(size_t)k * 128 + n]));
        o.y = __uint_as_float(f2tf32(W2[(size_t)(k + 4) * 128 + n]));
        Bf2[i2] = o;
    }
}

// ---------------------------------------------------------------------------
// Fused encoder: per CTA = 16 rows, 256 threads (8 warps).
//   B: z GEMM (tf32 mma) -> gates in registers -> Q = [h,c] in smem
//   C: s2 GEMM -> S2 (= s2 + b2 + w1b) in smem
//   D: WARP-LOCAL. warp w owns rows {2w, 2w+1}. lane=(half,node).
//      D1 node values in regs; D2 DCT via shfl; D3 Clenshaw + 16-lane softmax.
//   Only 3 CTA barriers total.
// ---------------------------------------------------------------------------
#define XS  132
#define QS  260
#define SS  132

#define OFF_X   0
#define OFF_Q   (16 * XS)              // 2112
#define OFF_S2  (OFF_Q + 16 * QS)      // 6272
#define OFF_WV  (OFF_S2 + 16 * SS)     // 8384
#define OFF_BL  (OFF_WV + 256)         // 8640
#define OFF_BB  (OFF_BL + 384)         // 9024
#define OFF_CM  (OFF_BB + 128)         // 9152  (CMT[j][m] = cos(m*(2j+1)pi/32))
#define SMEM_FLOATS (OFF_CM + 256)     // 9408 -> 37632 bytes (static)

__global__ void __launch_bounds__(256)
fused_enc(const float* __restrict__ x,
          const float2* __restrict__ Bf1, const float2* __restrict__ Bf2,
          const float* __restrict__ bl,  const float* __restrict__ b2,
          const float* __restrict__ w1,  const float* __restrict__ w1b,
          const float* __restrict__ v,   float* __restrict__ out)
{
    __shared__ float sm[SMEM_FLOATS];
    float*  X   = sm + OFF_X;
    float*  Q   = sm + OFF_Q;
    float*  S2  = sm + OFF_S2;
    float2* WV  = reinterpret_cast<float2*>(sm + OFF_WV);
    float*  BLs = sm + OFF_BL;
    float*  BB  = sm + OFF_BB;
    float*  CMT = sm + OFF_CM;

    const int tid  = threadIdx.x;
    const int lane = tid & 31;
    const int w    = tid >> 5;          // 0..7
    const int r0   = blockIdx.x * 16;

    // ---- load x strip + broadcast vectors + DCT matrix ----
    #pragma unroll
    for (int it = 0; it < 2; ++it) {
        int i = it * 256 + tid;          // < 512
        int row = i >> 5, q4 = i & 31;
        float4 vv = *reinterpret_cast<const float4*>(
            x + (size_t)(r0 + row) * 128 + q4 * 4);
        *reinterpret_cast<float4*>(&X[row * XS + q4 * 4]) = vv;
    }
    {   // CMT[j*16+m] = cos(m*(2j+1)*pi/32)
        int j = tid >> 4, m = tid & 15;
        CMT[tid] = cospif((float)(m * (2 * j + 1)) / 32.0f);
    }
    if (tid < 128) {
        WV[tid] = make_float2(w1[tid], v[tid]);
        BLs[tid]       = bl[tid];          // i bias
        BLs[128 + tid] = bl[256 + tid];    // g bias
        BLs[256 + tid] = bl[384 + tid];    // o bias
        BB[tid] = b2[tid] + w1b[tid];
    }
    __syncthreads();

    // ---- Phase B: z GEMM + in-register gates -> Q ----
    {
        float acc[6][4];
        #pragma unroll
        for (int j = 0; j < 6; ++j)
            #pragma unroll
            for (int e = 0; e < 4; ++e) acc[j][e] = 0.f;

        const int arow = lane >> 2, acol0 = lane & 3;
        #pragma unroll
        for (int t = 0; t < 16; ++t) {
            int ac = acol0 + t * 8;
            uint32_t a0 = f2tf32(X[arow * XS + ac]);
            uint32_t a1 = f2tf32(X[(arow + 8) * XS + ac]);
            uint32_t a2 = f2tf32(X[arow * XS + ac + 4]);
            uint32_t a3 = f2tf32(X[(arow + 8) * XS + ac + 4]);
            const float2* bp = Bf1 + (size_t)(t * 48 + w * 6) * 32 + lane;
            #pragma unroll
            for (int j = 0; j < 6; ++j) {
                float2 b = bp[j * 32];
                mma_tf32(acc[j], a0, a1, a2, a3,
                         __float_as_uint(b.x), __float_as_uint(b.y));
            }
        }

        const int crow = lane >> 2, cc = 2 * (lane & 3);
        #pragma unroll
        for (int jj = 0; jj < 2; ++jj) {
            const int u0 = w * 16 + jj * 8 + cc;
            const float bi0 = BLs[u0],       bi1 = BLs[u0 + 1];
            const float bg0 = BLs[128 + u0], bg1 = BLs[128 + u0 + 1];
            const float bo0 = BLs[256 + u0], bo1 = BLs[256 + u0 + 1];
            #pragma unroll
            for (int half = 0; half < 2; ++half) {
                const int row = crow + 8 * half;
                float iv0 = acc[jj][2*half]       + bi0;
                float iv1 = acc[jj][2*half + 1]   + bi1;
                float gv0 = acc[2+jj][2*half]     + bg0;
                float gv1 = acc[2+jj][2*half + 1] + bg1;
                float ov0 = acc[4+jj][2*half]     + bo0;
                float ov1 = acc[4+jj][2*half + 1] + bo1;
                float c0 = (0.5f * tanh_fast(0.5f * iv0) + 0.5f) * tanh_fast(gv0);
                float c1 = (0.5f * tanh_fast(0.5f * iv1) + 0.5f) * tanh_fast(gv1);
                float h0 = (0.5f * tanh_fast(0.5f * ov0) + 0.5f) * tanh_fast(c0);
                float h1 = (0.5f * tanh_fast(0.5f * ov1) + 0.5f) * tanh_fast(c1);
                *reinterpret_cast<float2*>(&Q[row * QS + u0])       = make_float2(h0, h1);
                *reinterpret_cast<float2*>(&Q[row * QS + 128 + u0]) = make_float2(c0, c1);
            }
        }
    }
    __syncthreads();

    // ---- Phase C: s2 GEMM (16 x 128, K=256) -> S2 = s2 + b2 + w1b ----
    {
        float acc[2][4];
        #pragma unroll
        for (int j = 0; j < 2; ++j)
            #pragma unroll
            for (int e = 0; e < 4; ++e) acc[j][e] = 0.f;

        const int arow = lane >> 2, acol0 = lane & 3;
        #pragma unroll
        for (int t = 0; t < 32; ++t) {
            int ac = acol0 + t * 8;
            uint32_t a0 = f2tf32(Q[arow * QS + ac]);
            uint32_t a1 = f2tf32(Q[(arow + 8) * QS + ac]);
            uint32_t a2 = f2tf32(Q[arow * QS + ac + 4]);
            uint32_t a3 = f2tf32(Q[(arow + 8) * QS + ac + 4]);
            const float2* bp = Bf2 + (size_t)(t * 16 + w * 2) * 32 + lane;
            #pragma unroll
            for (int j = 0; j < 2; ++j) {
                float2 b = bp[j * 32];
                mma_tf32(acc[j], a0, a1, a2, a3,
                         __float_as_uint(b.x), __float_as_uint(b.y));
            }
        }
        const int crow = lane >> 2, cc = 2 * (lane & 3);
        #pragma unroll
        for (int j = 0; j < 2; ++j) {
            int col = w * 16 + j * 8 + cc;
            float bb0 = BB[col], bb1 = BB[col + 1];
            *reinterpret_cast<float2*>(&S2[crow * SS + col]) =
                make_float2(acc[j][0] + bb0, acc[j][1] + bb1);
            *reinterpret_cast<float2*>(&S2[(crow + 8) * SS + col]) =
                make_float2(acc[j][2] + bb0, acc[j][3] + bb1);
        }
    }
    __syncthreads();

    // ---- Phase D: warp-local. warp w owns rows {2w, 2w+1}. ----
    {
        const int half = lane >> 4;          // row within pair
        const int j    = lane & 15;          // node / coeff / n-base index
        const int row  = 2 * w + half;
        const int base = lane & 16;          // shfl base for own half

        // D1: node value f(t_j) = sum_k v_k tanh(w1_k t_j + S2[row][k])
        const float tj = 8.0f * CMT[j * 16 + 1];
        const float* br = &S2[row * SS];
        float f0 = 0.f, f1 = 0.f, f2 = 0.f, f3 = 0.f;
        #pragma unroll 8
        for (int k = 0; k < 128; k += 4) {
            float2 wv0 = WV[k+0]; float b0 = br[k+0];
            float2 wv1 = WV[k+1]; float b1 = br[k+1];
            float2 wv2 = WV[k+2]; float b2v = br[k+2];
            float2 wv3 = WV[k+3]; float b3 = br[k+3];
            f0 = fmaf(tanh_fast(fmaf(wv0.x, tj, b0)),  wv0.y, f0);
            f1 = fmaf(tanh_fast(fmaf(wv1.x, tj, b1)),  wv1.y, f1);
            f2 = fmaf(tanh_fast(fmaf(wv2.x, tj, b2v)), wv2.y, f2);
            f3 = fmaf(tanh_fast(fmaf(wv3.x, tj, b3)),  wv3.y, f3);
        }
        float F = (f0 + f1) + (f2 + f3);

        // D2: Chebyshev coefficient a_j (this lane holds coeff index m = j)
        float am = 0.f;
        #pragma unroll
        for (int jj = 0; jj < 16; ++jj) {
            float fj = __shfl_sync(0xffffffffu, F, base | jj);
            am = fmaf(fj, CMT[jj * 16 + j], am);
        }
        am *= (j == 0) ? 0.0625f : 0.125f;

        // D3: gather all 16 coeffs, Clenshaw per n, softmax, output
        float a[16];
        #pragma unroll
        for (int m = 0; m < 16; ++m)
            a[m] = __shfl_sync(0xffffffffu, am, base | m);

        const float* xr = &X[row * XS + j];
        float xv[8], ea[8];
        #pragma unroll
        for (int q = 0; q < 8; ++q) xv[q] = xr[16 * q];

        #pragma unroll
        for (int q = 0; q < 8; ++q) {
            float t  = xv[q] * 0.125f;
            float tt = t + t;
            float c1 = a[15], c2 = 0.f;
            #pragma unroll
            for (int m = 14; m >= 1; --m) {
                float cn = fmaf(tt, c1, a[m] - c2);
                c2 = c1; c1 = cn;
            }
            ea[q] = fmaf(t, c1, a[0] - c2);
        }

        float mx = ea[0];
        #pragma unroll
        for (int q = 1; q < 8; ++q) mx = fmaxf(mx, ea[q]);
        #pragma unroll
        for (int o = 8; o > 0; o >>= 1)
            mx = fmaxf(mx, __shfl_xor_sync(0xffffffffu, mx, o));

        float p[8], s = 0.f;
        #pragma unroll
        for (int q = 0; q < 8; ++q) { p[q] = __expf(ea[q] - mx); s += p[q]; }
        #pragma unroll
        for (int o = 8; o > 0; o >>= 1)
            s += __shfl_xor_sync(0xffffffffu, s, o);
        float inv = 1.f / s;

        float* orow = out + (size_t)(r0 + row) * 128 + j;
        #pragma unroll
        for (int q = 0; q < 8; ++q)
            orow[16 * q] = xv[q] * p[q] * inv;
    }
}

// ---------------------------------------------------------------------------
extern "C" void kernel_launch(void* const* d_in, const int* in_sizes, int n_in,
                              void* d_out, int out_size)
{
    const float* x   = (const float*)d_in[0];
    const float* Wl  = (const float*)d_in[3];   // (128, 512)
    const float* bl  = (const float*)d_in[4];   // (512)
    const float* w1  = (const float*)d_in[5];   // (128)
    const float* w1b = (const float*)d_in[6];   // (128)
    const float* W2  = (const float*)d_in[7];   // (256, 128)
    const float* b2  = (const float*)d_in[8];   // (128)
    const float* v   = (const float*)d_in[9];   // (128)
    float* out = (float*)d_out;

    float2 *bf1, *bf2;
    cudaGetSymbolAddress((void**)&bf1, g_Bf1);
    cudaGetSymbolAddress((void**)&bf2, g_Bf2);

    pack_all<<<160, 256>>>(Wl, W2, bf1, bf2);   // 40960 threads
    fused_enc<<<ROWS / 16, 256>>>(x, bf1, bf2, bl, b2, w1, w1b, v, out);
}

// round 10
// speedup vs baseline: 4.5497x; 1.2620x over previous
#include <cuda_runtime.h>
#include <cstdint>
#include <math.h>

// Problem constants: B=64, T=128, N=128, U=128
#define ROWS 8192   // B*T

// Prepacked bf16 weight fragments (device globals -- no allocations allowed)
__device__ uint2 g_Bf1[8 * 48 * 32];    // Wl packed (K=128 -> 8 k16-steps, N=384)
__device__ uint2 g_Bf2[16 * 16 * 32];   // W2 packed (K=256 -> 16 k16-steps, N=128)

// ---------------------------------------------------------------------------
// helpers
// ---------------------------------------------------------------------------
__device__ __forceinline__ float tanh_fast(float x) {
    float y;
    asm("tanh.approx.f32 %0, %1;" : "=f"(y) : "f"(x));
    return y;
}
// pack two fp32 -> bf16x2 (lo = first/lower-k element)
__device__ __forceinline__ uint32_t packbf(float lo, float hi) {
    uint32_t r;
    asm("cvt.rn.bf16x2.f32 %0, %1, %2;" : "=r"(r) : "f"(hi), "f"(lo));
    return r;
}
__device__ __forceinline__ void mma_bf16(float c[4], uint32_t a0, uint32_t a1,
                                         uint32_t a2, uint32_t a3,
                                         uint32_t b0, uint32_t b1) {
    asm volatile(
        "mma.sync.aligned.m16n8k16.row.col.f32.bf16.bf16.f32 "
        "{%0,%1,%2,%3}, {%4,%5,%6,%7}, {%8,%9}, {%0,%1,%2,%3};"
        : "+f"(c[0]), "+f"(c[1]), "+f"(c[2]), "+f"(c[3])
        : "r"(a0), "r"(a1), "r"(a2), "r"(a3), "r"(b0), "r"(b1));
}

// ---------------------------------------------------------------------------
// One-shot pack of both weight matrices to bf16 m16n8k16 B-fragments.
// Bf1: t in 0..7 (k16 steps), J = w*6+j gate-interleaved (see round 4):
//   n = gate*128 + w*16 + jj*8 + (l>>2); orig col = n (+128 if n>=128).
//   k0 = t*16 + (l&3)*2; b0 = {W[k0][c], W[k0+1][c]}, b1 = {W[k0+8][c], W[k0+9][c]}
// Bf2: t in 0..15, n = j*8 + (l>>2), same k pattern over W2 (256x128).
// ---------------------------------------------------------------------------
__global__ void pack_all(const float* __restrict__ Wl, const float* __restrict__ W2,
                         uint2* __restrict__ Bf1, uint2* __restrict__ Bf2)
{
    int idx = blockIdx.x * 256 + threadIdx.x;
    if (idx < 8 * 48 * 32) {
        int t = idx / (48 * 32);
        int rem = idx % (48 * 32);
        int J = rem >> 5, l = rem & 31;
        int w = J / 6, j = J % 6;
        int gate = j >> 1, jj = j & 1;
        int n = gate * 128 + w * 16 + jj * 8 + (l >> 2);
        int col = n + ((n >= 128) ? 128 : 0);
        int k0 = t * 16 + (l & 3) * 2;
        uint2 o;
        o.x = packbf(Wl[(size_t)k0 * 512 + col],       Wl[(size_t)(k0 + 1) * 512 + col]);
        o.y = packbf(Wl[(size_t)(k0 + 8) * 512 + col], Wl[(size_t)(k0 + 9) * 512 + col]);
        Bf1[idx] = o;
    } else if (idx < 8 * 48 * 32 + 16 * 16 * 32) {
        int i2 = idx - 8 * 48 * 32;
        int t = i2 / (16 * 32);
        int rem = i2 % (16 * 32);
        int j = rem >> 5, l = rem & 31;
        int n = j * 8 + (l >> 2);
        int k0 = t * 16 + (l & 3) * 2;
        uint2 o;
        o.x = packbf(W2[(size_t)k0 * 128 + n],       W2[(size_t)(k0 + 1) * 128 + n]);
        o.y = packbf(W2[(size_t)(k0 + 8) * 128 + n], W2[(size_t)(k0 + 9) * 128 + n]);
        Bf2[i2] = o;
    }
}

// ---------------------------------------------------------------------------
// Fused encoder: per CTA = 16 rows, 256 threads (8 warps).
//   B: z = x @ Wl (bf16 m16n8k16 mma) -> gates in regs -> QB (bf16x2) in smem
//   C: s2 = q @ W2 -> S2 (= s2 + b2 + w1b, fp32) in smem
//   D: warp-local Chebyshev attention (see round 9).
// ---------------------------------------------------------------------------
#define XS   132   // x fp32 stride
#define XBS  68    // x bf16x2 stride (uint32)
#define QBS  132   // query bf16x2 stride (uint32, 128 + pad)
#define SS   132

#define OFF_X   0
#define OFF_XB  (16 * XS)              // 2112
#define OFF_QB  (OFF_XB + 16 * XBS)    // 3200
#define OFF_S2  (OFF_QB + 16 * QBS)    // 5312
#define OFF_WV  (OFF_S2 + 16 * SS)     // 7424
#define OFF_BL  (OFF_WV + 256)         // 7680
#define OFF_BB  (OFF_BL + 384)         // 8064
#define OFF_CM  (OFF_BB + 128)         // 8192
#define SMEM_FLOATS (OFF_CM + 256)     // 8448 -> 33792 bytes (static)

__global__ void __launch_bounds__(256)
fused_enc(const float* __restrict__ x,
          const uint2* __restrict__ Bf1, const uint2* __restrict__ Bf2,
          const float* __restrict__ bl,  const float* __restrict__ b2,
          const float* __restrict__ w1,  const float* __restrict__ w1b,
          const float* __restrict__ v,   float* __restrict__ out)
{
    __shared__ float sm[SMEM_FLOATS];
    float*     X   = sm + OFF_X;
    uint32_t*  XB  = reinterpret_cast<uint32_t*>(sm + OFF_XB);
    uint32_t*  QB  = reinterpret_cast<uint32_t*>(sm + OFF_QB);
    float*     S2  = sm + OFF_S2;
    float2*    WV  = reinterpret_cast<float2*>(sm + OFF_WV);
    float*     BLs = sm + OFF_BL;
    float*     BB  = sm + OFF_BB;
    float*     CMT = sm + OFF_CM;

    const int tid  = threadIdx.x;
    const int lane = tid & 31;
    const int w    = tid >> 5;          // 0..7
    const int r0   = blockIdx.x * 16;

    // ---- load x strip (fp32 + bf16x2 shadow) + broadcast vectors + DCT ----
    #pragma unroll
    for (int it = 0; it < 2; ++it) {
        int i = it * 256 + tid;          // < 512
        int row = i >> 5, q4 = i & 31;
        float4 vv = *reinterpret_cast<const float4*>(
            x + (size_t)(r0 + row) * 128 + q4 * 4);
        *reinterpret_cast<float4*>(&X[row * XS + q4 * 4]) = vv;
        XB[row * XBS + q4 * 2]     = packbf(vv.x, vv.y);
        XB[row * XBS + q4 * 2 + 1] = packbf(vv.z, vv.w);
    }
    {   // CMT[j*16+m] = cos(m*(2j+1)*pi/32)
        int j = tid >> 4, m = tid & 15;
        CMT[tid] = cospif((float)(m * (2 * j + 1)) / 32.0f);
    }
    if (tid < 128) {
        WV[tid] = make_float2(w1[tid], v[tid]);
        BLs[tid]       = bl[tid];          // i bias
        BLs[128 + tid] = bl[256 + tid];    // g bias
        BLs[256 + tid] = bl[384 + tid];    // o bias
        BB[tid] = b2[tid] + w1b[tid];
    }
    __syncthreads();

    const int arow = lane >> 2;   // fragment row within 8-row group
    const int tig  = lane & 3;    // thread-in-group

    // ---- Phase B: z GEMM (8 k16-steps) + in-register gates -> QB ----
    {
        float acc[6][4];
        #pragma unroll
        for (int j = 0; j < 6; ++j)
            #pragma unroll
            for (int e = 0; e < 4; ++e) acc[j][e] = 0.f;

        #pragma unroll
        for (int t = 0; t < 8; ++t) {
            uint32_t a0 = XB[arow * XBS + t * 8 + tig];
            uint32_t a1 = XB[(arow + 8) * XBS + t * 8 + tig];
            uint32_t a2 = XB[arow * XBS + t * 8 + tig + 4];
            uint32_t a3 = XB[(arow + 8) * XBS + t * 8 + tig + 4];
            const uint2* bp = Bf1 + (size_t)(t * 48 + w * 6) * 32 + lane;
            #pragma unroll
            for (int j = 0; j < 6; ++j) {
                uint2 b = bp[j * 32];
                mma_bf16(acc[j], a0, a1, a2, a3, b.x, b.y);
            }
        }

        const int crow = arow, cc = 2 * tig;
        #pragma unroll
        for (int jj = 0; jj < 2; ++jj) {
            const int u0 = w * 16 + jj * 8 + cc;       // pair (u0, u0+1)
            const int kk = u0 >> 1;                    // bf16x2 column index
            const float bi0 = BLs[u0],       bi1 = BLs[u0 + 1];
            const float bg0 = BLs[128 + u0], bg1 = BLs[128 + u0 + 1];
            const float bo0 = BLs[256 + u0], bo1 = BLs[256 + u0 + 1];
            #pragma unroll
            for (int half = 0; half < 2; ++half) {
                const int row = crow + 8 * half;
                float iv0 = acc[jj][2*half]       + bi0;
                float iv1 = acc[jj][2*half + 1]   + bi1;
                float gv0 = acc[2+jj][2*half]     + bg0;
                float gv1 = acc[2+jj][2*half + 1] + bg1;
                float ov0 = acc[4+jj][2*half]     + bo0;
                float ov1 = acc[4+jj][2*half + 1] + bo1;
                float c0 = (0.5f * tanh_fast(0.5f * iv0) + 0.5f) * tanh_fast(gv0);
                float c1 = (0.5f * tanh_fast(0.5f * iv1) + 0.5f) * tanh_fast(gv1);
                float h0 = (0.5f * tanh_fast(0.5f * ov0) + 0.5f) * tanh_fast(c0);
                float h1 = (0.5f * tanh_fast(0.5f * ov1) + 0.5f) * tanh_fast(c1);
                QB[row * QBS + kk]      = packbf(h0, h1);   // h: k 0..127
                QB[row * QBS + 64 + kk] = packbf(c0, c1);   // c: k 128..255
            }
        }
    }
    __syncthreads();

    // ---- Phase C: s2 GEMM (16 k16-steps over K=256) -> S2 = s2 + b2 + w1b ----
    {
        float acc[2][4];
        #pragma unroll
        for (int j = 0; j < 2; ++j)
            #pragma unroll
            for (int e = 0; e < 4; ++e) acc[j][e] = 0.f;

        #pragma unroll
        for (int t = 0; t < 16; ++t) {
            uint32_t a0 = QB[arow * QBS + t * 8 + tig];
            uint32_t a1 = QB[(arow + 8) * QBS + t * 8 + tig];
            uint32_t a2 = QB[arow * QBS + t * 8 + tig + 4];
            uint32_t a3 = QB[(arow + 8) * QBS + t * 8 + tig + 4];
            const uint2* bp = Bf2 + (size_t)(t * 16 + w * 2) * 32 + lane;
            #pragma unroll
            for (int j = 0; j < 2; ++j) {
                uint2 b = bp[j * 32];
                mma_bf16(acc[j], a0, a1, a2, a3, b.x, b.y);
            }
        }
        const int crow = arow, cc = 2 * tig;
        #pragma unroll
        for (int j = 0; j < 2; ++j) {
            int col = w * 16 + j * 8 + cc;
            float bb0 = BB[col], bb1 = BB[col + 1];
            *reinterpret_cast<float2*>(&S2[crow * SS + col]) =
                make_float2(acc[j][0] + bb0, acc[j][1] + bb1);
            *reinterpret_cast<float2*>(&S2[(crow + 8) * SS + col]) =
                make_float2(acc[j][2] + bb0, acc[j][3] + bb1);
        }
    }
    __syncthreads();

    // ---- Phase D: warp-local. warp w owns rows {2w, 2w+1}. ----
    {
        const int half = lane >> 4;          // row within pair
        const int j    = lane & 15;          // node / coeff / n-base index
        const int row  = 2 * w + half;
        const int base = lane & 16;          // shfl base for own half

        // D1: node value f(t_j) = sum_k v_k tanh(w1_k t_j + S2[row][k])
        const float tj = 8.0f * CMT[j * 16 + 1];
        const float* br = &S2[row * SS];
        float f0 = 0.f, f1 = 0.f, f2 = 0.f, f3 = 0.f;
        #pragma unroll 8
        for (int k = 0; k < 128; k += 4) {
            float2 wv0 = WV[k+0]; float b0 = br[k+0];
            float2 wv1 = WV[k+1]; float b1 = br[k+1];
            float2 wv2 = WV[k+2]; float b2v = br[k+2];
            float2 wv3 = WV[k+3]; float b3 = br[k+3];
            f0 = fmaf(tanh_fast(fmaf(wv0.x, tj, b0)),  wv0.y, f0);
            f1 = fmaf(tanh_fast(fmaf(wv1.x, tj, b1)),  wv1.y, f1);
            f2 = fmaf(tanh_fast(fmaf(wv2.x, tj, b2v)), wv2.y, f2);
            f3 = fmaf(tanh_fast(fmaf(wv3.x, tj, b3)),  wv3.y, f3);
        }
        float F = (f0 + f1) + (f2 + f3);

        // D2: Chebyshev coefficient a_j via shfl-DCT
        float am = 0.f;
        #pragma unroll
        for (int jj = 0; jj < 16; ++jj) {
            float fj = __shfl_sync(0xffffffffu, F, base | jj);
            am = fmaf(fj, CMT[jj * 16 + j], am);
        }
        am *= (j == 0) ? 0.0625f : 0.125f;

        // D3: gather coeffs, Clenshaw per n, 16-lane softmax, output
        float a[16];
        #pragma unroll
        for (int m = 0; m < 16; ++m)
            a[m] = __shfl_sync(0xffffffffu, am, base | m);

        const float* xr = &X[row * XS + j];
        float xv[8], ea[8];
        #pragma unroll
        for (int q = 0; q < 8; ++q) xv[q] = xr[16 * q];

        #pragma unroll
        for (int q = 0; q < 8; ++q) {
            float t  = xv[q] * 0.125f;
            float tt = t + t;
            float c1 = a[15], c2 = 0.f;
            #pragma unroll
            for (int m = 14; m >= 1; --m) {
                float cn = fmaf(tt, c1, a[m] - c2);
                c2 = c1; c1 = cn;
            }
            ea[q] = fmaf(t, c1, a[0] - c2);
        }

        float mx = ea[0];
        #pragma unroll
        for (int q = 1; q < 8; ++q) mx = fmaxf(mx, ea[q]);
        #pragma unroll
        for (int o = 8; o > 0; o >>= 1)
            mx = fmaxf(mx, __shfl_xor_sync(0xffffffffu, mx, o));

        float p[8], s = 0.f;
        #pragma unroll
        for (int q = 0; q < 8; ++q) { p[q] = __expf(ea[q] - mx); s += p[q]; }
        #pragma unroll
        for (int o = 8; o > 0; o >>= 1)
            s += __shfl_xor_sync(0xffffffffu, s, o);
        float inv = 1.f / s;

        float* orow = out + (size_t)(r0 + row) * 128 + j;
        #pragma unroll
        for (int q = 0; q < 8; ++q)
            orow[16 * q] = xv[q] * p[q] * inv;
    }
}

// ---------------------------------------------------------------------------
extern "C" void kernel_launch(void* const* d_in, const int* in_sizes, int n_in,
                              void* d_out, int out_size)
{
    const float* x   = (const float*)d_in[0];
    const float* Wl  = (const float*)d_in[3];   // (128, 512)
    const float* bl  = (const float*)d_in[4];   // (512)
    const float* w1  = (const float*)d_in[5];   // (128)
    const float* w1b = (const float*)d_in[6];   // (128)
    const float* W2  = (const float*)d_in[7];   // (256, 128)
    const float* b2  = (const float*)d_in[8];   // (128)
    const float* v   = (const float*)d_in[9];   // (128)
    float* out = (float*)d_out;

    uint2 *bf1, *bf2;
    cudaGetSymbolAddress((void**)&bf1, g_Bf1);
    cudaGetSymbolAddress((void**)&bf2, g_Bf2);

    // 8*48*32 + 16*16*32 = 20480 threads -> 80 CTAs
    pack_all<<<80, 256>>>(Wl, W2, bf1, bf2);
    fused_enc<<<ROWS / 16, 256>>>(x, bf1, bf2, bl, b2, w1, w1b, v, out);
}